// round 7
// baseline (speedup 1.0000x reference)
#include <cuda_runtime.h>
#include <stdint.h>

#define NUSERS 50000
#define NITEMS 30000
#define NNODES 80000
#define EK 64
#define HH 32
#define NNZADJ 2000000
#define NNZR 1000000

// ---------------- scratch (device globals; allocation is forbidden) ----------------
__device__ float g_itf[2][NITEMS * EK];
__device__ float g_ihl[2][NITEMS * HH];
__device__ float g_uhl[2][NUSERS * HH];
__device__ float g_ih[2][NITEMS * HH];
__device__ float g_uh[2][NUSERS * HH];
__device__ float g_e0[NNODES * EK];      // cge
__device__ float g_e1[NNODES * EK];
__device__ float g_e2[NNODES * EK];
__device__ float g_m0[2][NUSERS * EK];
__device__ float g_m1[2][NNODES * EK];
__device__ float g_lat[2][HH * EK];

// ---------------- threefry2x32 (JAX-compatible, 20 rounds) ----------------
__host__ __device__ __forceinline__ void tf2x32(uint32_t k0, uint32_t k1,
                                                uint32_t x0, uint32_t x1,
                                                uint32_t* o0, uint32_t* o1) {
  uint32_t ks2 = k0 ^ k1 ^ 0x1BD11BDAu;
  uint32_t v0 = x0 + k0, v1 = x1 + k1;
#define TFR(r) { v0 += v1; v1 = (v1 << (r)) | (v1 >> (32 - (r))); v1 ^= v0; }
  TFR(13) TFR(15) TFR(26) TFR(6)
  v0 += k1;  v1 += ks2 + 1u;
  TFR(17) TFR(29) TFR(16) TFR(24)
  v0 += ks2; v1 += k0 + 2u;
  TFR(13) TFR(15) TFR(26) TFR(6)
  v0 += k0;  v1 += k1 + 3u;
  TFR(17) TFR(29) TFR(16) TFR(24)
  v0 += k1;  v1 += ks2 + 4u;
  TFR(13) TFR(15) TFR(26) TFR(6)
  v0 += ks2; v1 += k0 + 5u;
#undef TFR
  *o0 = v0; *o1 = v1;
}

// ---------------- vector atomic add ----------------
__device__ __forceinline__ void red_add_f4(float4* p, float4 v) {
  asm volatile("red.global.add.v4.f32 [%0], {%1,%2,%3,%4};"
               :: "l"(p), "f"(v.x), "f"(v.y), "f"(v.z), "f"(v.w) : "memory");
}

// ---------------- tf32 split + mma helpers ----------------
__device__ __forceinline__ uint2 tf32split2(float x) {
  uint32_t h;
  asm("cvt.rna.tf32.f32 %0, %1;" : "=r"(h) : "f"(x));
  float r = x - __uint_as_float(h);
  uint32_t l;
  asm("cvt.rna.tf32.f32 %0, %1;" : "=r"(l) : "f"(r));
  return make_uint2(h, l);
}

__device__ __forceinline__ void mma8(float* c, const uint32_t* a, const uint32_t* b) {
  asm volatile("mma.sync.aligned.m16n8k8.row.col.f32.tf32.tf32.f32 "
               "{%0,%1,%2,%3}, {%4,%5,%6,%7}, {%8,%9}, {%0,%1,%2,%3};"
               : "+f"(c[0]), "+f"(c[1]), "+f"(c[2]), "+f"(c[3])
               : "r"(a[0]), "r"(a[1]), "r"(a[2]), "r"(a[3]), "r"(b[0]), "r"(b[1]));
}

// ---------------- SpMM: (edge,col4)-per-thread (coalesced), y pre-zeroed ----------------
template <int C4>
__global__ void spmm_kernel(const int* __restrict__ rows, const int* __restrict__ cols,
                            const float* __restrict__ vals, const float4* __restrict__ x,
                            float4* __restrict__ y, int nnz) {
  int idx = blockIdx.x * 256 + threadIdx.x;
  if (idx >= nnz * C4) return;
  int e = idx / C4;
  int c = idx - e * C4;
  int r = __ldg(rows + e), cl = __ldg(cols + e);
  float v = __ldg(vals + e);
  float4 xv = __ldg(x + (size_t)cl * C4 + c);
  red_add_f4(y + (size_t)r * C4 + c, make_float4(v * xv.x, v * xv.y, v * xv.z, v * xv.w));
}

// both-modality r-spmm: blockIdx.y selects modality
template <int C4>
__global__ void spmm_r_both(const int* __restrict__ rows, const int* __restrict__ cols,
                            const float* __restrict__ vals,
                            const float4* __restrict__ x0, const float4* __restrict__ x1,
                            float4* __restrict__ y0, float4* __restrict__ y1, int nnz) {
  int idx = blockIdx.x * 256 + threadIdx.x;
  if (idx >= nnz * C4) return;
  const float4* x = blockIdx.y ? x1 : x0;
  float4* y = blockIdx.y ? y1 : y0;
  int e = idx / C4;
  int c = idx - e * C4;
  int r = __ldg(rows + e), cl = __ldg(cols + e);
  float v = __ldg(vals + e);
  float4 xv = __ldg(x + (size_t)cl * C4 + c);
  red_add_f4(y + (size_t)r * C4 + c, make_float4(v * xv.x, v * xv.y, v * xv.z, v * xv.w));
}

// first cge spmm: gather virtually from concat(Gu, Gi)
__global__ void spmm_cge1(const int* __restrict__ rows, const int* __restrict__ cols,
                          const float* __restrict__ vals, const float4* __restrict__ Gu,
                          const float4* __restrict__ Gi, float4* __restrict__ y, int nnz) {
  int idx = blockIdx.x * 256 + threadIdx.x;
  if (idx >= nnz * 16) return;
  int e = idx >> 4;
  int c = idx & 15;
  int r = __ldg(rows + e), cl = __ldg(cols + e);
  float v = __ldg(vals + e);
  const float4* xr = (cl < NUSERS) ? Gu + (size_t)cl * 16 : Gi + (size_t)(cl - NUSERS) * 16;
  float4 xv = __ldg(xr + c);
  red_add_f4(y + (size_t)r * 16 + c, make_float4(v * xv.x, v * xv.y, v * xv.z, v * xv.w));
}

// mge adj spmm, both modalities; gathers from (m0users*inv | itf)
__global__ void spmm_mge_both(const int* __restrict__ rows, const int* __restrict__ cols,
                              const float* __restrict__ vals,
                              const float4* __restrict__ m0A, const float4* __restrict__ m0B,
                              const float4* __restrict__ itfA, const float4* __restrict__ itfB,
                              const float* __restrict__ inv,
                              float4* __restrict__ y0, float4* __restrict__ y1, int nnz) {
  int idx = blockIdx.x * 256 + threadIdx.x;
  if (idx >= nnz * 16) return;
  const float4* m0  = blockIdx.y ? m0B : m0A;
  const float4* itf = blockIdx.y ? itfB : itfA;
  float4* y = blockIdx.y ? y1 : y0;
  int e = idx >> 4;
  int c = idx & 15;
  int r = __ldg(rows + e), cl = __ldg(cols + e);
  float v = __ldg(vals + e);
  const float4* xr;
  if (cl < NUSERS) { xr = m0 + (size_t)cl * 16; v *= __ldg(inv + cl); }
  else             { xr = itf + (size_t)(cl - NUSERS) * 16; }
  float4 xv = __ldg(xr + c);
  red_add_f4(y + (size_t)r * 16 + c, make_float4(v * xv.x, v * xv.y, v * xv.z, v * xv.w));
}

// ---------------- fused GEMM both modalities: 3xTF32, pre-split hi/lo in smem ----------------
// blockIdx.y: 0 = visual, 1 = text. Cf = A@Bt [64 cols], Cl = A@Bh [32 cols].
// Block 128x96, 8 warps as 4(row)x2(col); warp tile 32x48 = 2 m16 x 6 n8.
// smem: As2[k][row] (32x132 uint2), Bs2[k][col] (32x100 uint2); {hi,lo} per element.
#define AS_STRIDE 132
#define BS_STRIDE 100
#define GEMM_SMEM ((32 * AS_STRIDE + 32 * BS_STRIDE) * (int)sizeof(uint2))
__global__ __launch_bounds__(256, 2)
void gemm_both_kernel(const float* __restrict__ A0, const float* __restrict__ A1,
                      const float* __restrict__ Bt0, const float* __restrict__ Bt1,
                      const float* __restrict__ Bh0, const float* __restrict__ Bh1,
                      float* __restrict__ Cf0, float* __restrict__ Cf1,
                      float* __restrict__ Cl0, float* __restrict__ Cl1,
                      int F0, int F1) {
  extern __shared__ uint2 smem2[];
  uint2* As2 = smem2;                     // [32][AS_STRIDE]
  uint2* Bs2 = smem2 + 32 * AS_STRIDE;    // [32][BS_STRIDE]
  const int mmod = blockIdx.y;
  const float* A  = mmod ? A1 : A0;
  const float* Bt = mmod ? Bt1 : Bt0;
  const float* Bh = mmod ? Bh1 : Bh0;
  float* Cf = mmod ? Cf1 : Cf0;
  float* Cl = mmod ? Cl1 : Cl0;
  const int F = mmod ? F1 : F0;

  const int row0 = blockIdx.x * 128;
  const int tid = threadIdx.x;
  const int wid = tid >> 5, lane = tid & 31;
  const int wr = wid >> 1, wc = wid & 1;
  const int qid = lane >> 2, qtid = lane & 3;

  // global->reg prefetch
  const int lr = tid >> 1;            // load row 0..127
  const int lk = (tid & 1) * 16;      // load k offset
  const int gr_l = row0 + lr;
  const bool rok = gr_l < NITEMS;
  const float* Arow = A + (size_t)gr_l * F + lk;

  float4 a4[4];
  float bb[12];
  const float4 z4 = make_float4(0.f, 0.f, 0.f, 0.f);
#pragma unroll
  for (int i = 0; i < 4; i++) a4[i] = rok ? __ldg((const float4*)(Arow + 4 * i)) : z4;
#pragma unroll
  for (int i = 0; i < 12; i++) {
    int idx = tid + 256 * i, kk = idx / 96, c = idx - kk * 96;
    bb[i] = (c < 64) ? __ldg(Bt + kk * 64 + c) : __ldg(Bh + kk * 32 + (c - 64));
  }

  float acc[2][6][4];
#pragma unroll
  for (int mt = 0; mt < 2; mt++)
#pragma unroll
    for (int nt = 0; nt < 6; nt++)
#pragma unroll
      for (int j = 0; j < 4; j++) acc[mt][nt][j] = 0.0f;

  for (int k0 = 0; k0 < F; k0 += 32) {
    // stage + split once per element
#pragma unroll
    for (int i = 0; i < 4; i++) {
      As2[(lk + 4 * i + 0) * AS_STRIDE + lr] = tf32split2(a4[i].x);
      As2[(lk + 4 * i + 1) * AS_STRIDE + lr] = tf32split2(a4[i].y);
      As2[(lk + 4 * i + 2) * AS_STRIDE + lr] = tf32split2(a4[i].z);
      As2[(lk + 4 * i + 3) * AS_STRIDE + lr] = tf32split2(a4[i].w);
    }
#pragma unroll
    for (int i = 0; i < 12; i++) {
      int idx = tid + 256 * i, kk = idx / 96, c = idx - kk * 96;
      Bs2[kk * BS_STRIDE + c] = tf32split2(bb[i]);
    }
    __syncthreads();
    int kn = k0 + 32;
    if (kn < F) {
#pragma unroll
      for (int i = 0; i < 4; i++) a4[i] = rok ? __ldg((const float4*)(Arow + kn + 4 * i)) : z4;
#pragma unroll
      for (int i = 0; i < 12; i++) {
        int idx = tid + 256 * i, kk = idx / 96, c = idx - kk * 96;
        bb[i] = (c < 64) ? __ldg(Bt + (kn + kk) * 64 + c) : __ldg(Bh + (kn + kk) * 32 + (c - 64));
      }
    }
#pragma unroll
    for (int ks = 0; ks < 4; ks++) {
      const int kb = ks * 8;
      uint2 a2[2][4];
#pragma unroll
      for (int mt = 0; mt < 2; mt++) {
        int ar = wr * 32 + mt * 16 + qid;
        a2[mt][0] = As2[(kb + qtid) * AS_STRIDE + ar];
        a2[mt][1] = As2[(kb + qtid) * AS_STRIDE + ar + 8];
        a2[mt][2] = As2[(kb + qtid + 4) * AS_STRIDE + ar];
        a2[mt][3] = As2[(kb + qtid + 4) * AS_STRIDE + ar + 8];
      }
#pragma unroll
      for (int nt = 0; nt < 6; nt++) {
        int bn = wc * 48 + nt * 8 + qid;
        uint2 b0 = Bs2[(kb + qtid) * BS_STRIDE + bn];
        uint2 b1 = Bs2[(kb + qtid + 4) * BS_STRIDE + bn];
        uint32_t bh[2] = {b0.x, b1.x};
        uint32_t bl[2] = {b0.y, b1.y};
#pragma unroll
        for (int mt = 0; mt < 2; mt++) {
          uint32_t ah[4] = {a2[mt][0].x, a2[mt][1].x, a2[mt][2].x, a2[mt][3].x};
          uint32_t al[4] = {a2[mt][0].y, a2[mt][1].y, a2[mt][2].y, a2[mt][3].y};
          mma8(acc[mt][nt], ah, bh);
          mma8(acc[mt][nt], ah, bl);
          mma8(acc[mt][nt], al, bh);
        }
      }
    }
    __syncthreads();
  }

  // epilogue: c0,c1 at row qid; c2,c3 at row qid+8; cols 2*qtid, 2*qtid+1
#pragma unroll
  for (int mt = 0; mt < 2; mt++) {
    int gr = row0 + wr * 32 + mt * 16 + qid;
#pragma unroll
    for (int nt = 0; nt < 6; nt++) {
      int cc = wc * 48 + nt * 8 + 2 * qtid;
      if (gr < NITEMS) {
        if (cc < 64) { Cf[gr * 64 + cc] = acc[mt][nt][0]; Cf[gr * 64 + cc + 1] = acc[mt][nt][1]; }
        else         { Cl[gr * 32 + cc - 64] = acc[mt][nt][0]; Cl[gr * 32 + cc - 63] = acc[mt][nt][1]; }
      }
      if (gr + 8 < NITEMS) {
        if (cc < 64) { Cf[(gr + 8) * 64 + cc] = acc[mt][nt][2]; Cf[(gr + 8) * 64 + cc + 1] = acc[mt][nt][3]; }
        else         { Cl[(gr + 8) * 32 + cc - 64] = acc[mt][nt][2]; Cl[(gr + 8) * 32 + cc - 63] = acc[mt][nt][3]; }
      }
    }
  }
}

// ---------------- gumbel softmax both modalities, warp per row ----------------
__global__ void gumbel_both_kernel(const float* __restrict__ lg0, const float* __restrict__ lg1,
                                   float* __restrict__ o0, float* __restrict__ o1, int rows,
                                   unsigned k00, unsigned k01, unsigned k10, unsigned k11) {
  int row = blockIdx.x * 8 + (threadIdx.x >> 5);
  if (row >= rows) return;
  const float* logits = blockIdx.y ? lg1 : lg0;
  float* out = blockIdx.y ? o1 : o0;
  unsigned k0 = blockIdx.y ? k10 : k00;
  unsigned k1 = blockIdx.y ? k11 : k01;
  int lane = threadIdx.x & 31;
  unsigned idx = (unsigned)row * 32u + (unsigned)lane;
  unsigned b0, b1;
  tf2x32(k0, k1, 0u, idx, &b0, &b1);
  unsigned bits = b0 ^ b1;
  float f = __uint_as_float((bits >> 9) | 0x3f800000u) - 1.0f;
  const float TINY = 1.1754943508222875e-38f;
  float u = fmaxf(TINY, f + TINY);
  float g = -logf(-logf(u));
  float z = (logits[row * 32 + lane] + g) * 5.0f;   // /tau, tau=0.2
  float mx = z;
#pragma unroll
  for (int s = 16; s; s >>= 1) mx = fmaxf(mx, __shfl_xor_sync(0xffffffffu, mx, s));
  float e = expf(z - mx);
  float sm = e;
#pragma unroll
  for (int s = 16; s; s >>= 1) sm += __shfl_xor_sync(0xffffffffu, sm, s);
  out[row * 32 + lane] = e / sm;
}

// ---------------- cge combine: cge = (concat(Gu,Gi) + e1 + e2)/3 ----------------
__global__ void cge_combine_kernel(const float* __restrict__ Gu, const float* __restrict__ Gi,
                                   const float* __restrict__ e1, const float* __restrict__ e2,
                                   float* __restrict__ cge) {
  int idx = blockIdx.x * 256 + threadIdx.x;
  if (idx >= NNODES * EK) return;
  float ego = (idx < NUSERS * EK) ? Gu[idx] : Gi[idx - NUSERS * EK];
  cge[idx] = (ego + e1[idx] + e2[idx]) * (1.0f / 3.0f);
}

// ---------------- lat[32,64] += ih^T @ icge, both modalities (lat pre-zeroed) ----------------
__global__ void lat_both_kernel(const float* __restrict__ w0, const float* __restrict__ w1,
                                const float* __restrict__ icge,
                                float* __restrict__ lat0, float* __restrict__ lat1, int chunk) {
  const float* w = blockIdx.y ? w1 : w0;
  float* lat = blockIdx.y ? lat1 : lat0;
  int lane = threadIdx.x & 31;
  int kg = threadIdx.x >> 5;  // 0..7
  int start = blockIdx.x * chunk;
  int end = min(start + chunk, NITEMS);
  float acc[8] = {0, 0, 0, 0, 0, 0, 0, 0};
  for (int it = start; it < end; ++it) {
    float wv = w[it * HH + lane];
    const float* cr = icge + it * EK + kg * 8;
#pragma unroll
    for (int j = 0; j < 8; j++) acc[j] = fmaf(wv, __ldg(cr + j), acc[j]);
  }
#pragma unroll
  for (int j = 0; j < 8; j++) atomicAdd(&lat[lane * EK + kg * 8 + j], acc[j]);
}

// ---------------- hyper apply, all 4 outputs in one launch ----------------
#define IBLK ((NITEMS * EK + 255) / 256)
#define UBLK ((NUSERS * EK + 255) / 256)
__global__ void hyper_apply_all(const float* __restrict__ ih0, const float* __restrict__ ih1,
                                const float* __restrict__ uh0, const float* __restrict__ uh1,
                                const float* __restrict__ lat0, const float* __restrict__ lat1,
                                float* __restrict__ outIV, float* __restrict__ outIT,
                                float* __restrict__ outUV, float* __restrict__ outUT) {
  __shared__ float sl[HH * EK];
  const float* lat = blockIdx.y ? lat1 : lat0;
  for (int t = threadIdx.x; t < HH * EK; t += 256) sl[t] = lat[t];
  __syncthreads();
  const float* w;
  float* out;
  int idx;
  if (blockIdx.x < IBLK) {
    w = blockIdx.y ? ih1 : ih0;
    out = blockIdx.y ? outIT : outIV;
    idx = blockIdx.x * 256 + threadIdx.x;
    if (idx >= NITEMS * EK) return;
  } else {
    w = blockIdx.y ? uh1 : uh0;
    out = blockIdx.y ? outUT : outUV;
    idx = (blockIdx.x - IBLK) * 256 + threadIdx.x;
    if (idx >= NUSERS * EK) return;
  }
  int r = idx >> 6, k = idx & 63;
  float s = 0.0f;
#pragma unroll
  for (int h = 0; h < HH; h++) s = fmaf(w[r * HH + h], sl[h * EK + k], s);
  out[idx] = s;
}

// ---------------- final: out = cge + l2n(m1a) + l2n(m1b) + 0.2*l2n(ghe) ----------------
__global__ void final_kernel(float* __restrict__ out, const float* __restrict__ cge,
                             const float* __restrict__ m1a, const float* __restrict__ m1b) {
  const int OI   = NUSERS * EK;
  const int OHVU = (NUSERS + NITEMS) * EK;
  const int OHVI = OHVU + NUSERS * EK;
  const int OHTU = OHVI + NITEMS * EK;
  const int OHTI = OHTU + NUSERS * EK;
  int row = blockIdx.x * 8 + (threadIdx.x >> 5);
  if (row >= NNODES) return;
  int lane = threadIdx.x & 31;
  const float* hv;
  const float* ht;
  float* dst;
  if (row < NUSERS) {
    hv = out + OHVU + row * EK; ht = out + OHTU + row * EK; dst = out + row * EK;
  } else {
    int ir = row - NUSERS;
    hv = out + OHVI + ir * EK;  ht = out + OHTI + ir * EK;  dst = out + OI + ir * EK;
  }
  int b = row * EK;
  float a0 = m1a[b + lane], a1 = m1a[b + lane + 32];
  float c0 = m1b[b + lane], c1 = m1b[b + lane + 32];
  float g0 = hv[lane] + ht[lane];
  float g1 = hv[lane + 32] + ht[lane + 32];
  float sa = a0 * a0 + a1 * a1;
  float sc = c0 * c0 + c1 * c1;
  float sg = g0 * g0 + g1 * g1;
#pragma unroll
  for (int s = 16; s; s >>= 1) {
    sa += __shfl_xor_sync(0xffffffffu, sa, s);
    sc += __shfl_xor_sync(0xffffffffu, sc, s);
    sg += __shfl_xor_sync(0xffffffffu, sg, s);
  }
  float ia = 1.0f / fmaxf(sqrtf(sa), 1e-12f);
  float ic = 1.0f / fmaxf(sqrtf(sc), 1e-12f);
  float ig = 0.2f / fmaxf(sqrtf(sg), 1e-12f);
  dst[lane]      = cge[b + lane]      + a0 * ia + c0 * ic + g0 * ig;
  dst[lane + 32] = cge[b + lane + 32] + a1 * ia + c1 * ic + g1 * ig;
}

// ================================================================================
extern "C" void kernel_launch(void* const* d_in, const int* in_sizes, int n_in,
                              void* d_out, int out_size) {
  const float* Gu       = (const float*)d_in[0];
  const float* Gi       = (const float*)d_in[1];
  const float* feat_v   = (const float*)d_in[2];
  const float* feat_t   = (const float*)d_in[3];
  const float* trs_v    = (const float*)d_in[4];
  const float* trs_t    = (const float*)d_in[5];
  const float* hyp_v    = (const float*)d_in[6];
  const float* hyp_t    = (const float*)d_in[7];
  const float* inv      = (const float*)d_in[8];
  const float* adj_vals = (const float*)d_in[9];
  const float* r_vals   = (const float*)d_in[10];
  const int*   adj_rows = (const int*)d_in[11];
  const int*   adj_cols = (const int*)d_in[12];
  const int*   r_rows   = (const int*)d_in[13];
  const int*   r_cols   = (const int*)d_in[14];
  float* out = (float*)d_out;
  int Fv = in_sizes[2] / NITEMS;
  int Ft = in_sizes[3] / NITEMS;

  float *p_itf, *p_ihl, *p_uhl, *p_ih, *p_uh, *p_e0, *p_e1, *p_e2, *p_m0, *p_m1, *p_lat;
  cudaGetSymbolAddress((void**)&p_itf, g_itf);
  cudaGetSymbolAddress((void**)&p_ihl, g_ihl);
  cudaGetSymbolAddress((void**)&p_uhl, g_uhl);
  cudaGetSymbolAddress((void**)&p_ih,  g_ih);
  cudaGetSymbolAddress((void**)&p_uh,  g_uh);
  cudaGetSymbolAddress((void**)&p_e0,  g_e0);
  cudaGetSymbolAddress((void**)&p_e1,  g_e1);
  cudaGetSymbolAddress((void**)&p_e2,  g_e2);
  cudaGetSymbolAddress((void**)&p_m0,  g_m0);
  cudaGetSymbolAddress((void**)&p_m1,  g_m1);
  cudaGetSymbolAddress((void**)&p_lat, g_lat);
  float* p_itfT = p_itf + NITEMS * EK;
  float* p_ihlT = p_ihl + NITEMS * HH;
  float* p_uhlT = p_uhl + NUSERS * HH;
  float* p_ihT  = p_ih + NITEMS * HH;
  float* p_uhT  = p_uh + NUSERS * HH;
  float* p_m0T  = p_m0 + NUSERS * EK;
  float* p_m1T  = p_m1 + NNODES * EK;
  float* p_latT = p_lat + HH * EK;

  cudaFuncSetAttribute(gemm_both_kernel, cudaFuncAttributeMaxDynamicSharedMemorySize, GEMM_SMEM);

  // JAX threefry keys (host arithmetic; deterministic)
  uint32_t ki0[2], ki1[2], ku0[2], ku1[2];
  for (int m = 0; m < 2; m++) {
    uint32_t km0, km1;
    tf2x32(0u, 42u, 0u, (uint32_t)m, &km0, &km1);   // fold_in(key(42), m)
    tf2x32(km0, km1, 0u, 0u, &ki0[m], &ki1[m]);     // split -> k1 (i_hyper)
    tf2x32(km0, km1, 0u, 1u, &ku0[m], &ku1[m]);     // split -> k2 (u_hyper)
  }

  const size_t NB  = (size_t)NNODES * EK * sizeof(float);
  const size_t UB  = (size_t)NUSERS * EK * sizeof(float);
  const size_t UHB = (size_t)NUSERS * HH * sizeof(float);
  const int GADJ16 = (NNZADJ * 16 + 255) / 256;
  const int GR8    = (NNZR * 8 + 255) / 256;
  const int GR16   = (NNZR * 16 + 255) / 256;
  const int GN     = (NNODES * EK + 255) / 256;
  const int OHVU = (NUSERS + NITEMS) * EK;
  const int OHVI = OHVU + NUSERS * EK;
  const int OHTU = OHVI + NITEMS * EK;
  const int OHTI = OHTU + NUSERS * EK;

  // ---- all scratch zeroing up front ----
  cudaMemsetAsync(p_e1, 0, NB, 0);
  cudaMemsetAsync(p_e2, 0, NB, 0);
  cudaMemsetAsync(p_uhl, 0, 2 * UHB, 0);
  cudaMemsetAsync(p_m0, 0, 2 * UB, 0);
  cudaMemsetAsync(p_m1, 0, 2 * NB, 0);
  cudaMemsetAsync(p_lat, 0, 2 * HH * EK * sizeof(float), 0);

  // ---- both GEMMs in one launch (3xTF32 tensor cores, pre-split smem) ----
  gemm_both_kernel<<<dim3((NITEMS + 127) / 128, 2), 256, GEMM_SMEM>>>(
      feat_v, feat_t, trs_v, trs_t, hyp_v, hyp_t,
      p_itf, p_itfT, p_ihl, p_ihlT, Fv, Ft);

  // ---- cge chain ----
  spmm_cge1<<<GADJ16, 256>>>(adj_rows, adj_cols, adj_vals,
                             (const float4*)Gu, (const float4*)Gi, (float4*)p_e1, NNZADJ);
  spmm_kernel<16><<<GADJ16, 256>>>(adj_rows, adj_cols, adj_vals,
                                   (const float4*)p_e1, (float4*)p_e2, NNZADJ);
  cge_combine_kernel<<<GN, 256>>>(Gu, Gi, p_e1, p_e2, p_e0);

  // ---- gumbel (items) both modalities ----
  gumbel_both_kernel<<<dim3((NITEMS + 7) / 8, 2), 256>>>(
      p_ihl, p_ihlT, p_ih, p_ihT, NITEMS, ki0[0], ki1[0], ki0[1], ki1[1]);

  // ---- r-spmms, both modalities ----
  spmm_r_both<8><<<dim3(GR8, 2), 256>>>(r_rows, r_cols, r_vals,
                                        (const float4*)p_ihl, (const float4*)p_ihlT,
                                        (float4*)p_uhl, (float4*)p_uhlT, NNZR);
  gumbel_both_kernel<<<dim3((NUSERS + 7) / 8, 2), 256>>>(
      p_uhl, p_uhlT, p_uh, p_uhT, NUSERS, ku0[0], ku1[0], ku0[1], ku1[1]);
  spmm_r_both<16><<<dim3(GR16, 2), 256>>>(r_rows, r_cols, r_vals,
                                          (const float4*)p_itf, (const float4*)p_itfT,
                                          (float4*)p_m0, (float4*)p_m0T, NNZR);

  // ---- mge adj spmm, both modalities ----
  spmm_mge_both<<<dim3(GADJ16, 2), 256>>>(adj_rows, adj_cols, adj_vals,
                                          (const float4*)p_m0, (const float4*)p_m0T,
                                          (const float4*)p_itf, (const float4*)p_itfT,
                                          inv, (float4*)p_m1, (float4*)p_m1T, NNZADJ);

  // ---- hyper path ----
  lat_both_kernel<<<dim3(120, 2), 256>>>(p_ih, p_ihT, p_e0 + NUSERS * EK, p_lat, p_latT, 250);
  hyper_apply_all<<<dim3(IBLK + UBLK, 2), 256>>>(
      p_ih, p_ihT, p_uh, p_uhT, p_lat, p_latT,
      out + OHVI, out + OHTI, out + OHVU, out + OHTU);

  final_kernel<<<(NNODES + 7) / 8, 256>>>(out, p_e0, p_m1, p_m1T);
}

// round 8
// speedup vs baseline: 1.2362x; 1.2362x over previous
#include <cuda_runtime.h>
#include <stdint.h>

#define NUSERS 50000
#define NITEMS 30000
#define NNODES 80000
#define EK 64
#define HH 32
#define NNZADJ 2000000
#define NNZR 1000000
#define NCHA ((NNODES + 1023) / 1024)
#define NCHR ((NUSERS + 1023) / 1024)

// ---------------- scratch (device globals; allocation is forbidden) ----------------
__device__ float g_itf[2][NITEMS * EK];
__device__ float g_ihl[2][NITEMS * HH];
__device__ float g_uhl[2][NUSERS * HH];
__device__ float g_ih[2][NITEMS * HH];
__device__ float g_uh[2][NUSERS * HH];
__device__ float g_e0[NNODES * EK];      // cge
__device__ float g_e1[NNODES * EK];
__device__ float g_e2[NNODES * EK];
__device__ float g_m0[2][NUSERS * EK];
__device__ float g_m1[2][NNODES * EK];
__device__ float g_lat[2][HH * EK];
// CSR scratch
__device__ int   g_startA[NNODES + 1];   // doubles as histogram counts
__device__ int   g_curA[NNODES];
__device__ int   g_scolA[NNZADJ];
__device__ float g_svalA[NNZADJ];
__device__ int   g_csumA[NCHA];
__device__ int   g_coffA[NCHA];
__device__ int   g_startR[NUSERS + 1];
__device__ int   g_curR[NUSERS];
__device__ int   g_scolR[NNZR];
__device__ float g_svalR[NNZR];
__device__ int   g_csumR[NCHR];
__device__ int   g_coffR[NCHR];

// ---------------- threefry2x32 (JAX-compatible, 20 rounds) ----------------
__host__ __device__ __forceinline__ void tf2x32(uint32_t k0, uint32_t k1,
                                                uint32_t x0, uint32_t x1,
                                                uint32_t* o0, uint32_t* o1) {
  uint32_t ks2 = k0 ^ k1 ^ 0x1BD11BDAu;
  uint32_t v0 = x0 + k0, v1 = x1 + k1;
#define TFR(r) { v0 += v1; v1 = (v1 << (r)) | (v1 >> (32 - (r))); v1 ^= v0; }
  TFR(13) TFR(15) TFR(26) TFR(6)
  v0 += k1;  v1 += ks2 + 1u;
  TFR(17) TFR(29) TFR(16) TFR(24)
  v0 += ks2; v1 += k0 + 2u;
  TFR(13) TFR(15) TFR(26) TFR(6)
  v0 += k0;  v1 += k1 + 3u;
  TFR(17) TFR(29) TFR(16) TFR(24)
  v0 += k1;  v1 += ks2 + 4u;
  TFR(13) TFR(15) TFR(26) TFR(6)
  v0 += ks2; v1 += k0 + 5u;
#undef TFR
  *o0 = v0; *o1 = v1;
}

// ---------------- tf32 split + mma helpers ----------------
__device__ __forceinline__ void tf32split(float x, uint32_t& hi, uint32_t& lo) {
  uint32_t h;
  asm("cvt.rna.tf32.f32 %0, %1;" : "=r"(h) : "f"(x));
  float r = x - __uint_as_float(h);
  uint32_t l;
  asm("cvt.rna.tf32.f32 %0, %1;" : "=r"(l) : "f"(r));
  hi = h; lo = l;
}

__device__ __forceinline__ void mma8(float* c, const uint32_t* a, const uint32_t* b) {
  asm volatile("mma.sync.aligned.m16n8k8.row.col.f32.tf32.tf32.f32 "
               "{%0,%1,%2,%3}, {%4,%5,%6,%7}, {%8,%9}, {%0,%1,%2,%3};"
               : "+f"(c[0]), "+f"(c[1]), "+f"(c[2]), "+f"(c[3])
               : "r"(a[0]), "r"(a[1]), "r"(a[2]), "r"(a[3]), "r"(b[0]), "r"(b[1]));
}

// ================= CSR build (counting sort by row) =================
__global__ void csr_hist(const int* __restrict__ rows, int nnz, int* __restrict__ cnt) {
  int e = blockIdx.x * 256 + threadIdx.x;
  if (e < nnz) atomicAdd(&cnt[__ldg(rows + e)], 1);
}

__global__ void csr_chunksum(const int* __restrict__ cnt, int* __restrict__ csum, int n) {
  __shared__ int ts[256];
  int base = blockIdx.x * 1024;
  int s = 0;
  for (int i = threadIdx.x; i < 1024; i += 256) {
    int idx = base + i;
    s += (idx < n) ? cnt[idx] : 0;
  }
  ts[threadIdx.x] = s;
  __syncthreads();
  for (int off = 128; off; off >>= 1) {
    if (threadIdx.x < off) ts[threadIdx.x] += ts[threadIdx.x + off];
    __syncthreads();
  }
  if (threadIdx.x == 0) csum[blockIdx.x] = ts[0];
}

__global__ void csr_scanchunks(const int* __restrict__ csum, int* __restrict__ coff,
                               int* __restrict__ start, int nch, int n, int nnz) {
  if (threadIdx.x == 0 && blockIdx.x == 0) {
    int run = 0;
    for (int i = 0; i < nch; i++) { coff[i] = run; run += csum[i]; }
    start[n] = nnz;
  }
}

// scans cnt within each 1024-chunk; writes exclusive prefix into start (may alias cnt)
__global__ void csr_chunkscan(const int* __restrict__ cnt, const int* __restrict__ coff,
                              int* __restrict__ start, int n) {
  __shared__ int sm[1024];
  __shared__ int ts[256];
  int base = blockIdx.x * 1024;
  for (int i = threadIdx.x; i < 1024; i += 256)
    sm[i] = (base + i < n) ? cnt[base + i] : 0;
  __syncthreads();
  int t = threadIdx.x;
  int a0 = sm[t * 4], a1 = sm[t * 4 + 1], a2 = sm[t * 4 + 2], a3 = sm[t * 4 + 3];
  int local = a0 + a1 + a2 + a3;
  ts[t] = local;
  __syncthreads();
  for (int off = 1; off < 256; off <<= 1) {
    int v = (t >= off) ? ts[t - off] : 0;
    __syncthreads();
    ts[t] += v;
    __syncthreads();
  }
  int excl = ts[t] - local + coff[blockIdx.x];
  if (base + t * 4 + 0 < n) start[base + t * 4 + 0] = excl;
  if (base + t * 4 + 1 < n) start[base + t * 4 + 1] = excl + a0;
  if (base + t * 4 + 2 < n) start[base + t * 4 + 2] = excl + a0 + a1;
  if (base + t * 4 + 3 < n) start[base + t * 4 + 3] = excl + a0 + a1 + a2;
}

__global__ void csr_scatter(const int* __restrict__ rows, const int* __restrict__ cols,
                            const float* __restrict__ vals, int* __restrict__ cursor,
                            int* __restrict__ scol, float* __restrict__ sval, int nnz) {
  int e = blockIdx.x * 256 + threadIdx.x;
  if (e >= nnz) return;
  int r = __ldg(rows + e);
  int p = atomicAdd(&cursor[r], 1);
  scol[p] = __ldg(cols + e);
  sval[p] = __ldg(vals + e);
}

// ================= CSR gather SpMMs (warp per row, no atomics) =================
// 64-col: lane holds float2
__global__ void spmm_csr64(const int* __restrict__ start, const int* __restrict__ scol,
                           const float* __restrict__ sval, const float2* __restrict__ x,
                           float2* __restrict__ y, int nrows) {
  int row = blockIdx.x * 8 + (threadIdx.x >> 5);
  if (row >= nrows) return;
  int lane = threadIdx.x & 31;
  int s = start[row], e = start[row + 1];
  float ax = 0.f, ay = 0.f;
  for (int i = s; i < e; i++) {
    int c = __ldg(scol + i);
    float v = __ldg(sval + i);
    float2 xv = __ldg(x + (size_t)c * 32 + lane);
    ax = fmaf(v, xv.x, ax); ay = fmaf(v, xv.y, ay);
  }
  y[(size_t)row * 32 + lane] = make_float2(ax, ay);
}

// first cge pass: x = concat(Gu, Gi)
__global__ void spmm_csr_cge1(const int* __restrict__ start, const int* __restrict__ scol,
                              const float* __restrict__ sval, const float2* __restrict__ Gu,
                              const float2* __restrict__ Gi, float2* __restrict__ y) {
  int row = blockIdx.x * 8 + (threadIdx.x >> 5);
  if (row >= NNODES) return;
  int lane = threadIdx.x & 31;
  int s = start[row], e = start[row + 1];
  float ax = 0.f, ay = 0.f;
  for (int i = s; i < e; i++) {
    int c = __ldg(scol + i);
    float v = __ldg(sval + i);
    const float2* xr = (c < NUSERS) ? Gu + (size_t)c * 32 : Gi + (size_t)(c - NUSERS) * 32;
    float2 xv = __ldg(xr + lane);
    ax = fmaf(v, xv.x, ax); ay = fmaf(v, xv.y, ay);
  }
  y[(size_t)row * 32 + lane] = make_float2(ax, ay);
}

// mge adj pass, both modalities (blockIdx.y): gathers from (m0users*inv | itf)
__global__ void spmm_csr_mge_both(const int* __restrict__ start, const int* __restrict__ scol,
                                  const float* __restrict__ sval,
                                  const float2* __restrict__ m0A, const float2* __restrict__ m0B,
                                  const float2* __restrict__ itfA, const float2* __restrict__ itfB,
                                  const float* __restrict__ inv,
                                  float2* __restrict__ y0, float2* __restrict__ y1) {
  int row = blockIdx.x * 8 + (threadIdx.x >> 5);
  if (row >= NNODES) return;
  const float2* m0  = blockIdx.y ? m0B : m0A;
  const float2* itf = blockIdx.y ? itfB : itfA;
  float2* y = blockIdx.y ? y1 : y0;
  int lane = threadIdx.x & 31;
  int s = start[row], e = start[row + 1];
  float ax = 0.f, ay = 0.f;
  for (int i = s; i < e; i++) {
    int c = __ldg(scol + i);
    float v = __ldg(sval + i);
    const float2* xr;
    if (c < NUSERS) { xr = m0 + (size_t)c * 32; v *= __ldg(inv + c); }
    else            { xr = itf + (size_t)(c - NUSERS) * 32; }
    float2 xv = __ldg(xr + lane);
    ax = fmaf(v, xv.x, ax); ay = fmaf(v, xv.y, ay);
  }
  y[(size_t)row * 32 + lane] = make_float2(ax, ay);
}

// r-spmm 64-col, both modalities (itf -> m0)
__global__ void spmm_csr64_both(const int* __restrict__ start, const int* __restrict__ scol,
                                const float* __restrict__ sval,
                                const float2* __restrict__ x0, const float2* __restrict__ x1,
                                float2* __restrict__ y0, float2* __restrict__ y1, int nrows) {
  int row = blockIdx.x * 8 + (threadIdx.x >> 5);
  if (row >= nrows) return;
  const float2* x = blockIdx.y ? x1 : x0;
  float2* y = blockIdx.y ? y1 : y0;
  int lane = threadIdx.x & 31;
  int s = start[row], e = start[row + 1];
  float ax = 0.f, ay = 0.f;
  for (int i = s; i < e; i++) {
    int c = __ldg(scol + i);
    float v = __ldg(sval + i);
    float2 xv = __ldg(x + (size_t)c * 32 + lane);
    ax = fmaf(v, xv.x, ax); ay = fmaf(v, xv.y, ay);
  }
  y[(size_t)row * 32 + lane] = make_float2(ax, ay);
}

// r-spmm 32-col, both modalities (ihl -> uhl): lane holds 1 float
__global__ void spmm_csr32_both(const int* __restrict__ start, const int* __restrict__ scol,
                                const float* __restrict__ sval,
                                const float* __restrict__ x0, const float* __restrict__ x1,
                                float* __restrict__ y0, float* __restrict__ y1, int nrows) {
  int row = blockIdx.x * 8 + (threadIdx.x >> 5);
  if (row >= nrows) return;
  const float* x = blockIdx.y ? x1 : x0;
  float* y = blockIdx.y ? y1 : y0;
  int lane = threadIdx.x & 31;
  int s = start[row], e = start[row + 1];
  float a = 0.f;
  for (int i = s; i < e; i++) {
    int c = __ldg(scol + i);
    float v = __ldg(sval + i);
    a = fmaf(v, __ldg(x + (size_t)c * 32 + lane), a);
  }
  y[(size_t)row * 32 + lane] = a;
}

// ---------------- fused GEMM both modalities (round-6 version: measured best) ----------------
__global__ __launch_bounds__(256, 2)
void gemm_both_kernel(const float* __restrict__ A0, const float* __restrict__ A1,
                      const float* __restrict__ Bt0, const float* __restrict__ Bt1,
                      const float* __restrict__ Bh0, const float* __restrict__ Bh1,
                      float* __restrict__ Cf0, float* __restrict__ Cf1,
                      float* __restrict__ Cl0, float* __restrict__ Cl1,
                      int F0, int F1) {
  __shared__ float As[32][129];
  __shared__ float Bs[32][97];
  const int mmod = blockIdx.y;
  const float* A  = mmod ? A1 : A0;
  const float* Bt = mmod ? Bt1 : Bt0;
  const float* Bh = mmod ? Bh1 : Bh0;
  float* Cf = mmod ? Cf1 : Cf0;
  float* Cl = mmod ? Cl1 : Cl0;
  const int F = mmod ? F1 : F0;

  const int row0 = blockIdx.x * 128;
  const int tid = threadIdx.x;
  const int wid = tid >> 5, lane = tid & 31;
  const int wr = wid >> 1, wc = wid & 1;
  const int qid = lane >> 2, qtid = lane & 3;

  const int lr = tid >> 1;
  const int lk = (tid & 1) * 16;
  const int gr_l = row0 + lr;
  const bool rok = gr_l < NITEMS;
  const float* Arow = A + (size_t)gr_l * F + lk;

  float4 a4[4];
  float bb[12];
  const float4 z4 = make_float4(0.f, 0.f, 0.f, 0.f);
#pragma unroll
  for (int i = 0; i < 4; i++) a4[i] = rok ? __ldg((const float4*)(Arow + 4 * i)) : z4;
#pragma unroll
  for (int i = 0; i < 12; i++) {
    int idx = tid + 256 * i, kk = idx / 96, c = idx - kk * 96;
    bb[i] = (c < 64) ? __ldg(Bt + kk * 64 + c) : __ldg(Bh + kk * 32 + (c - 64));
  }

  float acc[2][6][4];
#pragma unroll
  for (int mt = 0; mt < 2; mt++)
#pragma unroll
    for (int nt = 0; nt < 6; nt++)
#pragma unroll
      for (int j = 0; j < 4; j++) acc[mt][nt][j] = 0.0f;

  for (int k0 = 0; k0 < F; k0 += 32) {
#pragma unroll
    for (int i = 0; i < 4; i++) {
      As[lk + 4 * i + 0][lr] = a4[i].x;
      As[lk + 4 * i + 1][lr] = a4[i].y;
      As[lk + 4 * i + 2][lr] = a4[i].z;
      As[lk + 4 * i + 3][lr] = a4[i].w;
    }
#pragma unroll
    for (int i = 0; i < 12; i++) {
      int idx = tid + 256 * i, kk = idx / 96, c = idx - kk * 96;
      Bs[kk][c] = bb[i];
    }
    __syncthreads();
    int kn = k0 + 32;
    if (kn < F) {
#pragma unroll
      for (int i = 0; i < 4; i++) a4[i] = rok ? __ldg((const float4*)(Arow + kn + 4 * i)) : z4;
#pragma unroll
      for (int i = 0; i < 12; i++) {
        int idx = tid + 256 * i, kk = idx / 96, c = idx - kk * 96;
        bb[i] = (c < 64) ? __ldg(Bt + (kn + kk) * 64 + c) : __ldg(Bh + (kn + kk) * 32 + (c - 64));
      }
    }
#pragma unroll
    for (int ks = 0; ks < 4; ks++) {
      const int kb = ks * 8;
      uint32_t ahi[2][4], alo[2][4];
#pragma unroll
      for (int mt = 0; mt < 2; mt++) {
        int ar = wr * 32 + mt * 16 + qid;
        tf32split(As[kb + qtid][ar],         ahi[mt][0], alo[mt][0]);
        tf32split(As[kb + qtid][ar + 8],     ahi[mt][1], alo[mt][1]);
        tf32split(As[kb + qtid + 4][ar],     ahi[mt][2], alo[mt][2]);
        tf32split(As[kb + qtid + 4][ar + 8], ahi[mt][3], alo[mt][3]);
      }
#pragma unroll
      for (int nt = 0; nt < 6; nt++) {
        int bn = wc * 48 + nt * 8 + qid;
        uint32_t bh[2], bl[2];
        tf32split(Bs[kb + qtid][bn],     bh[0], bl[0]);
        tf32split(Bs[kb + qtid + 4][bn], bh[1], bl[1]);
#pragma unroll
        for (int mt = 0; mt < 2; mt++) {
          mma8(acc[mt][nt], ahi[mt], bh);
          mma8(acc[mt][nt], ahi[mt], bl);
          mma8(acc[mt][nt], alo[mt], bh);
        }
      }
    }
    __syncthreads();
  }

#pragma unroll
  for (int mt = 0; mt < 2; mt++) {
    int gr = row0 + wr * 32 + mt * 16 + qid;
#pragma unroll
    for (int nt = 0; nt < 6; nt++) {
      int cc = wc * 48 + nt * 8 + 2 * qtid;
      if (gr < NITEMS) {
        if (cc < 64) { Cf[gr * 64 + cc] = acc[mt][nt][0]; Cf[gr * 64 + cc + 1] = acc[mt][nt][1]; }
        else         { Cl[gr * 32 + cc - 64] = acc[mt][nt][0]; Cl[gr * 32 + cc - 63] = acc[mt][nt][1]; }
      }
      if (gr + 8 < NITEMS) {
        if (cc < 64) { Cf[(gr + 8) * 64 + cc] = acc[mt][nt][2]; Cf[(gr + 8) * 64 + cc + 1] = acc[mt][nt][3]; }
        else         { Cl[(gr + 8) * 32 + cc - 64] = acc[mt][nt][2]; Cl[(gr + 8) * 32 + cc - 63] = acc[mt][nt][3]; }
      }
    }
  }
}

// ---------------- gumbel softmax both modalities, warp per row ----------------
__global__ void gumbel_both_kernel(const float* __restrict__ lg0, const float* __restrict__ lg1,
                                   float* __restrict__ o0, float* __restrict__ o1, int rows,
                                   unsigned k00, unsigned k01, unsigned k10, unsigned k11) {
  int row = blockIdx.x * 8 + (threadIdx.x >> 5);
  if (row >= rows) return;
  const float* logits = blockIdx.y ? lg1 : lg0;
  float* out = blockIdx.y ? o1 : o0;
  unsigned k0 = blockIdx.y ? k10 : k00;
  unsigned k1 = blockIdx.y ? k11 : k01;
  int lane = threadIdx.x & 31;
  unsigned idx = (unsigned)row * 32u + (unsigned)lane;
  unsigned b0, b1;
  tf2x32(k0, k1, 0u, idx, &b0, &b1);
  unsigned bits = b0 ^ b1;
  float f = __uint_as_float((bits >> 9) | 0x3f800000u) - 1.0f;
  const float TINY = 1.1754943508222875e-38f;
  float u = fmaxf(TINY, f + TINY);
  float g = -logf(-logf(u));
  float z = (logits[row * 32 + lane] + g) * 5.0f;
  float mx = z;
#pragma unroll
  for (int s = 16; s; s >>= 1) mx = fmaxf(mx, __shfl_xor_sync(0xffffffffu, mx, s));
  float e = expf(z - mx);
  float sm = e;
#pragma unroll
  for (int s = 16; s; s >>= 1) sm += __shfl_xor_sync(0xffffffffu, sm, s);
  out[row * 32 + lane] = e / sm;
}

// ---------------- cge combine ----------------
__global__ void cge_combine_kernel(const float* __restrict__ Gu, const float* __restrict__ Gi,
                                   const float* __restrict__ e1, const float* __restrict__ e2,
                                   float* __restrict__ cge) {
  int idx = blockIdx.x * 256 + threadIdx.x;
  if (idx >= NNODES * EK) return;
  float ego = (idx < NUSERS * EK) ? Gu[idx] : Gi[idx - NUSERS * EK];
  cge[idx] = (ego + e1[idx] + e2[idx]) * (1.0f / 3.0f);
}

// ---------------- lat[32,64] += ih^T @ icge, both modalities (lat pre-zeroed) ----------------
__global__ void lat_both_kernel(const float* __restrict__ w0, const float* __restrict__ w1,
                                const float* __restrict__ icge,
                                float* __restrict__ lat0, float* __restrict__ lat1, int chunk) {
  const float* w = blockIdx.y ? w1 : w0;
  float* lat = blockIdx.y ? lat1 : lat0;
  int lane = threadIdx.x & 31;
  int kg = threadIdx.x >> 5;
  int start = blockIdx.x * chunk;
  int end = min(start + chunk, NITEMS);
  float acc[8] = {0, 0, 0, 0, 0, 0, 0, 0};
  for (int it = start; it < end; ++it) {
    float wv = w[it * HH + lane];
    const float* cr = icge + it * EK + kg * 8;
#pragma unroll
    for (int j = 0; j < 8; j++) acc[j] = fmaf(wv, __ldg(cr + j), acc[j]);
  }
#pragma unroll
  for (int j = 0; j < 8; j++) atomicAdd(&lat[lane * EK + kg * 8 + j], acc[j]);
}

// ---------------- hyper apply, all 4 outputs in one launch ----------------
#define IBLK ((NITEMS * EK + 255) / 256)
#define UBLK ((NUSERS * EK + 255) / 256)
__global__ void hyper_apply_all(const float* __restrict__ ih0, const float* __restrict__ ih1,
                                const float* __restrict__ uh0, const float* __restrict__ uh1,
                                const float* __restrict__ lat0, const float* __restrict__ lat1,
                                float* __restrict__ outIV, float* __restrict__ outIT,
                                float* __restrict__ outUV, float* __restrict__ outUT) {
  __shared__ float sl[HH * EK];
  const float* lat = blockIdx.y ? lat1 : lat0;
  for (int t = threadIdx.x; t < HH * EK; t += 256) sl[t] = lat[t];
  __syncthreads();
  const float* w;
  float* out;
  int idx;
  if (blockIdx.x < IBLK) {
    w = blockIdx.y ? ih1 : ih0;
    out = blockIdx.y ? outIT : outIV;
    idx = blockIdx.x * 256 + threadIdx.x;
    if (idx >= NITEMS * EK) return;
  } else {
    w = blockIdx.y ? uh1 : uh0;
    out = blockIdx.y ? outUT : outUV;
    idx = (blockIdx.x - IBLK) * 256 + threadIdx.x;
    if (idx >= NUSERS * EK) return;
  }
  int r = idx >> 6, k = idx & 63;
  float s = 0.0f;
#pragma unroll
  for (int h = 0; h < HH; h++) s = fmaf(w[r * HH + h], sl[h * EK + k], s);
  out[idx] = s;
}

// ---------------- final ----------------
__global__ void final_kernel(float* __restrict__ out, const float* __restrict__ cge,
                             const float* __restrict__ m1a, const float* __restrict__ m1b) {
  const int OI   = NUSERS * EK;
  const int OHVU = (NUSERS + NITEMS) * EK;
  const int OHVI = OHVU + NUSERS * EK;
  const int OHTU = OHVI + NITEMS * EK;
  const int OHTI = OHTU + NUSERS * EK;
  int row = blockIdx.x * 8 + (threadIdx.x >> 5);
  if (row >= NNODES) return;
  int lane = threadIdx.x & 31;
  const float* hv;
  const float* ht;
  float* dst;
  if (row < NUSERS) {
    hv = out + OHVU + row * EK; ht = out + OHTU + row * EK; dst = out + row * EK;
  } else {
    int ir = row - NUSERS;
    hv = out + OHVI + ir * EK;  ht = out + OHTI + ir * EK;  dst = out + OI + ir * EK;
  }
  int b = row * EK;
  float a0 = m1a[b + lane], a1 = m1a[b + lane + 32];
  float c0 = m1b[b + lane], c1 = m1b[b + lane + 32];
  float g0 = hv[lane] + ht[lane];
  float g1 = hv[lane + 32] + ht[lane + 32];
  float sa = a0 * a0 + a1 * a1;
  float sc = c0 * c0 + c1 * c1;
  float sg = g0 * g0 + g1 * g1;
#pragma unroll
  for (int s = 16; s; s >>= 1) {
    sa += __shfl_xor_sync(0xffffffffu, sa, s);
    sc += __shfl_xor_sync(0xffffffffu, sc, s);
    sg += __shfl_xor_sync(0xffffffffu, sg, s);
  }
  float ia = 1.0f / fmaxf(sqrtf(sa), 1e-12f);
  float ic = 1.0f / fmaxf(sqrtf(sc), 1e-12f);
  float ig = 0.2f / fmaxf(sqrtf(sg), 1e-12f);
  dst[lane]      = cge[b + lane]      + a0 * ia + c0 * ic + g0 * ig;
  dst[lane + 32] = cge[b + lane + 32] + a1 * ia + c1 * ic + g1 * ig;
}

// ================================================================================
extern "C" void kernel_launch(void* const* d_in, const int* in_sizes, int n_in,
                              void* d_out, int out_size) {
  const float* Gu       = (const float*)d_in[0];
  const float* Gi       = (const float*)d_in[1];
  const float* feat_v   = (const float*)d_in[2];
  const float* feat_t   = (const float*)d_in[3];
  const float* trs_v    = (const float*)d_in[4];
  const float* trs_t    = (const float*)d_in[5];
  const float* hyp_v    = (const float*)d_in[6];
  const float* hyp_t    = (const float*)d_in[7];
  const float* inv      = (const float*)d_in[8];
  const float* adj_vals = (const float*)d_in[9];
  const float* r_vals   = (const float*)d_in[10];
  const int*   adj_rows = (const int*)d_in[11];
  const int*   adj_cols = (const int*)d_in[12];
  const int*   r_rows   = (const int*)d_in[13];
  const int*   r_cols   = (const int*)d_in[14];
  float* out = (float*)d_out;
  int Fv = in_sizes[2] / NITEMS;
  int Ft = in_sizes[3] / NITEMS;

  float *p_itf, *p_ihl, *p_uhl, *p_ih, *p_uh, *p_e0, *p_e1, *p_e2, *p_m0, *p_m1, *p_lat;
  int *pA_start, *pA_cur, *pA_scol, *pA_csum, *pA_coff;
  int *pR_start, *pR_cur, *pR_scol, *pR_csum, *pR_coff;
  float *pA_sval, *pR_sval;
  cudaGetSymbolAddress((void**)&p_itf, g_itf);
  cudaGetSymbolAddress((void**)&p_ihl, g_ihl);
  cudaGetSymbolAddress((void**)&p_uhl, g_uhl);
  cudaGetSymbolAddress((void**)&p_ih,  g_ih);
  cudaGetSymbolAddress((void**)&p_uh,  g_uh);
  cudaGetSymbolAddress((void**)&p_e0,  g_e0);
  cudaGetSymbolAddress((void**)&p_e1,  g_e1);
  cudaGetSymbolAddress((void**)&p_e2,  g_e2);
  cudaGetSymbolAddress((void**)&p_m0,  g_m0);
  cudaGetSymbolAddress((void**)&p_m1,  g_m1);
  cudaGetSymbolAddress((void**)&p_lat, g_lat);
  cudaGetSymbolAddress((void**)&pA_start, g_startA);
  cudaGetSymbolAddress((void**)&pA_cur,   g_curA);
  cudaGetSymbolAddress((void**)&pA_scol,  g_scolA);
  cudaGetSymbolAddress((void**)&pA_sval,  g_svalA);
  cudaGetSymbolAddress((void**)&pA_csum,  g_csumA);
  cudaGetSymbolAddress((void**)&pA_coff,  g_coffA);
  cudaGetSymbolAddress((void**)&pR_start, g_startR);
  cudaGetSymbolAddress((void**)&pR_cur,   g_curR);
  cudaGetSymbolAddress((void**)&pR_scol,  g_scolR);
  cudaGetSymbolAddress((void**)&pR_sval,  g_svalR);
  cudaGetSymbolAddress((void**)&pR_csum,  g_csumR);
  cudaGetSymbolAddress((void**)&pR_coff,  g_coffR);
  float* p_itfT = p_itf + NITEMS * EK;
  float* p_ihlT = p_ihl + NITEMS * HH;
  float* p_uhlT = p_uhl + NUSERS * HH;
  float* p_ihT  = p_ih + NITEMS * HH;
  float* p_uhT  = p_uh + NUSERS * HH;
  float* p_m0T  = p_m0 + NUSERS * EK;
  float* p_m1T  = p_m1 + NNODES * EK;
  float* p_latT = p_lat + HH * EK;

  // JAX threefry keys
  uint32_t ki0[2], ki1[2], ku0[2], ku1[2];
  for (int m = 0; m < 2; m++) {
    uint32_t km0, km1;
    tf2x32(0u, 42u, 0u, (uint32_t)m, &km0, &km1);
    tf2x32(km0, km1, 0u, 0u, &ki0[m], &ki1[m]);
    tf2x32(km0, km1, 0u, 1u, &ku0[m], &ku1[m]);
  }

  const int GADJE = (NNZADJ + 255) / 256;
  const int GRE   = (NNZR + 255) / 256;
  const int GN    = (NNODES * EK + 255) / 256;
  const int GNODE = (NNODES + 7) / 8;
  const int GUSER = (NUSERS + 7) / 8;
  const int OHVU = (NUSERS + NITEMS) * EK;
  const int OHVI = OHVU + NUSERS * EK;
  const int OHTU = OHVI + NITEMS * EK;
  const int OHTI = OHTU + NUSERS * EK;

  // ---- zero CSR histograms + lat ----
  cudaMemsetAsync(pA_start, 0, (NNODES + 1) * sizeof(int), 0);
  cudaMemsetAsync(pR_start, 0, (NUSERS + 1) * sizeof(int), 0);
  cudaMemsetAsync(p_lat, 0, 2 * HH * EK * sizeof(float), 0);

  // ---- both GEMMs ----
  gemm_both_kernel<<<dim3((NITEMS + 127) / 128, 2), 256>>>(
      feat_v, feat_t, trs_v, trs_t, hyp_v, hyp_t,
      p_itf, p_itfT, p_ihl, p_ihlT, Fv, Ft);

  // ---- CSR builds (adj + r) ----
  csr_hist<<<GADJE, 256>>>(adj_rows, NNZADJ, pA_start);
  csr_hist<<<GRE, 256>>>(r_rows, NNZR, pR_start);
  csr_chunksum<<<NCHA, 256>>>(pA_start, pA_csum, NNODES);
  csr_chunksum<<<NCHR, 256>>>(pR_start, pR_csum, NUSERS);
  csr_scanchunks<<<1, 32>>>(pA_csum, pA_coff, pA_start, NCHA, NNODES, NNZADJ);
  csr_scanchunks<<<1, 32>>>(pR_csum, pR_coff, pR_start, NCHR, NUSERS, NNZR);
  csr_chunkscan<<<NCHA, 256>>>(pA_start, pA_coff, pA_start, NNODES);
  csr_chunkscan<<<NCHR, 256>>>(pR_start, pR_coff, pR_start, NUSERS);
  cudaMemcpyAsync(pA_cur, pA_start, NNODES * sizeof(int), cudaMemcpyDeviceToDevice, 0);
  cudaMemcpyAsync(pR_cur, pR_start, NUSERS * sizeof(int), cudaMemcpyDeviceToDevice, 0);
  csr_scatter<<<GADJE, 256>>>(adj_rows, adj_cols, adj_vals, pA_cur, pA_scol, pA_sval, NNZADJ);
  csr_scatter<<<GRE, 256>>>(r_rows, r_cols, r_vals, pR_cur, pR_scol, pR_sval, NNZR);

  // ---- cge chain (gather) ----
  spmm_csr_cge1<<<GNODE, 256>>>(pA_start, pA_scol, pA_sval,
                                (const float2*)Gu, (const float2*)Gi, (float2*)p_e1);
  spmm_csr64<<<GNODE, 256>>>(pA_start, pA_scol, pA_sval,
                             (const float2*)p_e1, (float2*)p_e2, NNODES);
  cge_combine_kernel<<<GN, 256>>>(Gu, Gi, p_e1, p_e2, p_e0);

  // ---- gumbel (items) ----
  gumbel_both_kernel<<<dim3((NITEMS + 7) / 8, 2), 256>>>(
      p_ihl, p_ihlT, p_ih, p_ihT, NITEMS, ki0[0], ki1[0], ki0[1], ki1[1]);

  // ---- r-spmms (gather) ----
  spmm_csr32_both<<<dim3(GUSER, 2), 256>>>(pR_start, pR_scol, pR_sval,
                                           p_ihl, p_ihlT, p_uhl, p_uhlT, NUSERS);
  gumbel_both_kernel<<<dim3(GUSER, 2), 256>>>(
      p_uhl, p_uhlT, p_uh, p_uhT, NUSERS, ku0[0], ku1[0], ku0[1], ku1[1]);
  spmm_csr64_both<<<dim3(GUSER, 2), 256>>>(pR_start, pR_scol, pR_sval,
                                           (const float2*)p_itf, (const float2*)p_itfT,
                                           (float2*)p_m0, (float2*)p_m0T, NUSERS);

  // ---- mge adj pass (gather) ----
  spmm_csr_mge_both<<<dim3(GNODE, 2), 256>>>(pA_start, pA_scol, pA_sval,
                                             (const float2*)p_m0, (const float2*)p_m0T,
                                             (const float2*)p_itf, (const float2*)p_itfT,
                                             inv, (float2*)p_m1, (float2*)p_m1T);

  // ---- hyper path ----
  lat_both_kernel<<<dim3(120, 2), 256>>>(p_ih, p_ihT, p_e0 + NUSERS * EK, p_lat, p_latT, 250);
  hyper_apply_all<<<dim3(IBLK + UBLK, 2), 256>>>(
      p_ih, p_ihT, p_uh, p_uhT, p_lat, p_latT,
      out + OHVI, out + OHTI, out + OHVU, out + OHTU);

  final_kernel<<<GNODE, 256>>>(out, p_e0, p_m1, p_m1T);
}

// round 9
// speedup vs baseline: 1.2672x; 1.0251x over previous
#include <cuda_runtime.h>
#include <stdint.h>

#define NUSERS 50000
#define NITEMS 30000
#define NNODES 80000
#define EK 64
#define HH 32
#define NNZADJ 2000000
#define NNZR 1000000
#define NCHA ((NNODES + 1023) / 1024)
#define NCHR ((NUSERS + 1023) / 1024)

// ---------------- scratch (device globals; allocation is forbidden) ----------------
__device__ float g_itf[2][NITEMS * EK];
__device__ float g_ihl[2][NITEMS * HH];
__device__ float g_uhl[2][NUSERS * HH];
__device__ float g_ih[2][NITEMS * HH];
__device__ float g_uh[2][NUSERS * HH];
__device__ float g_e0[NNODES * EK];      // cge
__device__ float g_e1[NNODES * EK];
__device__ float g_m0[2][NUSERS * EK];
__device__ float g_m1[2][NNODES * EK];
__device__ float g_lat[2][HH * EK];
// CSR scratch
__device__ int   g_startA[NNODES + 1];   // doubles as histogram counts
__device__ int   g_curA[NNODES];
__device__ int   g_scolA[NNZADJ];
__device__ float g_svalA[NNZADJ];
__device__ int   g_csumA[NCHA];
__device__ int   g_coffA[NCHA];
__device__ int   g_startR[NUSERS + 1];
__device__ int   g_curR[NUSERS];
__device__ int   g_scolR[NNZR];
__device__ float g_svalR[NNZR];
__device__ int   g_csumR[NCHR];
__device__ int   g_coffR[NCHR];

// ---------------- threefry2x32 (JAX-compatible, 20 rounds) ----------------
__host__ __device__ __forceinline__ void tf2x32(uint32_t k0, uint32_t k1,
                                                uint32_t x0, uint32_t x1,
                                                uint32_t* o0, uint32_t* o1) {
  uint32_t ks2 = k0 ^ k1 ^ 0x1BD11BDAu;
  uint32_t v0 = x0 + k0, v1 = x1 + k1;
#define TFR(r) { v0 += v1; v1 = (v1 << (r)) | (v1 >> (32 - (r))); v1 ^= v0; }
  TFR(13) TFR(15) TFR(26) TFR(6)
  v0 += k1;  v1 += ks2 + 1u;
  TFR(17) TFR(29) TFR(16) TFR(24)
  v0 += ks2; v1 += k0 + 2u;
  TFR(13) TFR(15) TFR(26) TFR(6)
  v0 += k0;  v1 += k1 + 3u;
  TFR(17) TFR(29) TFR(16) TFR(24)
  v0 += k1;  v1 += ks2 + 4u;
  TFR(13) TFR(15) TFR(26) TFR(6)
  v0 += ks2; v1 += k0 + 5u;
#undef TFR
  *o0 = v0; *o1 = v1;
}

// ---------------- tf32 split + mma helpers ----------------
__device__ __forceinline__ void tf32split(float x, uint32_t& hi, uint32_t& lo) {
  uint32_t h;
  asm("cvt.rna.tf32.f32 %0, %1;" : "=r"(h) : "f"(x));
  float r = x - __uint_as_float(h);
  uint32_t l;
  asm("cvt.rna.tf32.f32 %0, %1;" : "=r"(l) : "f"(r));
  hi = h; lo = l;
}

__device__ __forceinline__ void mma8(float* c, const uint32_t* a, const uint32_t* b) {
  asm volatile("mma.sync.aligned.m16n8k8.row.col.f32.tf32.tf32.f32 "
               "{%0,%1,%2,%3}, {%4,%5,%6,%7}, {%8,%9}, {%0,%1,%2,%3};"
               : "+f"(c[0]), "+f"(c[1]), "+f"(c[2]), "+f"(c[3])
               : "r"(a[0]), "r"(a[1]), "r"(a[2]), "r"(a[3]), "r"(b[0]), "r"(b[1]));
}

// ================= CSR build (counting sort by row), merged A+R launches =================
__global__ void csr_hist2(const int* __restrict__ rowsA, const int* __restrict__ rowsB,
                          int nnzA, int nnzB, int gA,
                          int* __restrict__ cntA, int* __restrict__ cntB) {
  int b = blockIdx.x;
  if (b < gA) {
    int e = b * 256 + threadIdx.x;
    if (e < nnzA) atomicAdd(&cntA[__ldg(rowsA + e)], 1);
  } else {
    int e = (b - gA) * 256 + threadIdx.x;
    if (e < nnzB) atomicAdd(&cntB[__ldg(rowsB + e)], 1);
  }
}

__global__ void csr_chunksum2(const int* __restrict__ cntA, const int* __restrict__ cntB,
                              int* __restrict__ csumA, int* __restrict__ csumB,
                              int nA, int nB) {
  __shared__ int ts[256];
  const int* cnt;
  int* csum;
  int n, ch;
  if (blockIdx.x < NCHA) { cnt = cntA; csum = csumA; n = nA; ch = blockIdx.x; }
  else                   { cnt = cntB; csum = csumB; n = nB; ch = blockIdx.x - NCHA; }
  int base = ch * 1024;
  int s = 0;
  for (int i = threadIdx.x; i < 1024; i += 256) {
    int idx = base + i;
    s += (idx < n) ? cnt[idx] : 0;
  }
  ts[threadIdx.x] = s;
  __syncthreads();
  for (int off = 128; off; off >>= 1) {
    if (threadIdx.x < off) ts[threadIdx.x] += ts[threadIdx.x + off];
    __syncthreads();
  }
  if (threadIdx.x == 0) csum[ch] = ts[0];
}

__global__ void csr_scanchunks2(const int* __restrict__ csumA, int* __restrict__ coffA,
                                int* __restrict__ startA,
                                const int* __restrict__ csumB, int* __restrict__ coffB,
                                int* __restrict__ startB) {
  if (threadIdx.x != 0) return;
  if (blockIdx.x == 0) {
    int run = 0;
    for (int i = 0; i < NCHA; i++) { coffA[i] = run; run += csumA[i]; }
    startA[NNODES] = NNZADJ;
  } else {
    int run = 0;
    for (int i = 0; i < NCHR; i++) { coffB[i] = run; run += csumB[i]; }
    startB[NUSERS] = NNZR;
  }
}

__global__ void csr_chunkscan2(int* __restrict__ cntA, const int* __restrict__ coffA,
                               int* __restrict__ curA,
                               int* __restrict__ cntB, const int* __restrict__ coffB,
                               int* __restrict__ curB, int nA, int nB) {
  __shared__ int sm[1024];
  __shared__ int ts[256];
  int* cnt;
  const int* coff;
  int* cur;
  int n, ch;
  if (blockIdx.x < NCHA) { cnt = cntA; coff = coffA; cur = curA; n = nA; ch = blockIdx.x; }
  else                   { cnt = cntB; coff = coffB; cur = curB; n = nB; ch = blockIdx.x - NCHA; }
  int base = ch * 1024;
  for (int i = threadIdx.x; i < 1024; i += 256)
    sm[i] = (base + i < n) ? cnt[base + i] : 0;
  __syncthreads();
  int t = threadIdx.x;
  int a0 = sm[t * 4], a1 = sm[t * 4 + 1], a2 = sm[t * 4 + 2], a3 = sm[t * 4 + 3];
  int local = a0 + a1 + a2 + a3;
  ts[t] = local;
  __syncthreads();
  for (int off = 1; off < 256; off <<= 1) {
    int v = (t >= off) ? ts[t - off] : 0;
    __syncthreads();
    ts[t] += v;
    __syncthreads();
  }
  int excl = ts[t] - local + coff[ch];
  int i0 = base + t * 4;
  if (i0 + 0 < n) { cnt[i0 + 0] = excl;                cur[i0 + 0] = excl; }
  if (i0 + 1 < n) { cnt[i0 + 1] = excl + a0;           cur[i0 + 1] = excl + a0; }
  if (i0 + 2 < n) { cnt[i0 + 2] = excl + a0 + a1;      cur[i0 + 2] = excl + a0 + a1; }
  if (i0 + 3 < n) { cnt[i0 + 3] = excl + a0 + a1 + a2; cur[i0 + 3] = excl + a0 + a1 + a2; }
}

__global__ void csr_scatter2(const int* __restrict__ rowsA, const int* __restrict__ colsA,
                             const float* __restrict__ valsA, int* __restrict__ curA,
                             int* __restrict__ scolA, float* __restrict__ svalA,
                             const int* __restrict__ rowsB, const int* __restrict__ colsB,
                             const float* __restrict__ valsB, int* __restrict__ curB,
                             int* __restrict__ scolB, float* __restrict__ svalB,
                             int nnzA, int nnzB, int gA) {
  int b = blockIdx.x;
  if (b < gA) {
    int e = b * 256 + threadIdx.x;
    if (e >= nnzA) return;
    int r = __ldg(rowsA + e);
    int p = atomicAdd(&curA[r], 1);
    scolA[p] = __ldg(colsA + e);
    svalA[p] = __ldg(valsA + e);
  } else {
    int e = (b - gA) * 256 + threadIdx.x;
    if (e >= nnzB) return;
    int r = __ldg(rowsB + e);
    int p = atomicAdd(&curB[r], 1);
    scolB[p] = __ldg(colsB + e);
    svalB[p] = __ldg(valsB + e);
  }
}

// ================= CSR gather SpMMs (warp per row, 4x unrolled, no atomics) =================
#define GATHER4(XEXPR)                                                        \
  float ax = 0.f, ay = 0.f;                                                   \
  int i = s;                                                                  \
  for (; i + 3 < e; i += 4) {                                                 \
    int c0 = __ldg(scol + i), c1 = __ldg(scol + i + 1);                       \
    int c2 = __ldg(scol + i + 2), c3 = __ldg(scol + i + 3);                   \
    float v0 = __ldg(sval + i), v1 = __ldg(sval + i + 1);                     \
    float v2 = __ldg(sval + i + 2), v3 = __ldg(sval + i + 3);                 \
    float2 x0, x1, x2, x3;                                                    \
    { int c = c0; float& v = v0; x0 = (XEXPR); (void)v; }                     \
    { int c = c1; float& v = v1; x1 = (XEXPR); (void)v; }                     \
    { int c = c2; float& v = v2; x2 = (XEXPR); (void)v; }                     \
    { int c = c3; float& v = v3; x3 = (XEXPR); (void)v; }                     \
    ax = fmaf(v0, x0.x, ax); ay = fmaf(v0, x0.y, ay);                         \
    ax = fmaf(v1, x1.x, ax); ay = fmaf(v1, x1.y, ay);                         \
    ax = fmaf(v2, x2.x, ax); ay = fmaf(v2, x2.y, ay);                         \
    ax = fmaf(v3, x3.x, ax); ay = fmaf(v3, x3.y, ay);                         \
  }                                                                           \
  for (; i < e; i++) {                                                        \
    int c = __ldg(scol + i);                                                  \
    float v = __ldg(sval + i);                                                \
    float2 xv = (XEXPR);                                                      \
    ax = fmaf(v, xv.x, ax); ay = fmaf(v, xv.y, ay);                           \
  }

// 64-col gather
__global__ void spmm_csr64(const int* __restrict__ start, const int* __restrict__ scol,
                           const float* __restrict__ sval, const float2* __restrict__ x,
                           float2* __restrict__ y, int nrows) {
  int row = blockIdx.x * 8 + (threadIdx.x >> 5);
  if (row >= nrows) return;
  int lane = threadIdx.x & 31;
  int s = start[row], e = start[row + 1];
  GATHER4(__ldg(x + (size_t)c * 32 + lane))
  y[(size_t)row * 32 + lane] = make_float2(ax, ay);
}

// first cge pass: x = concat(Gu, Gi)
__global__ void spmm_csr_cge1(const int* __restrict__ start, const int* __restrict__ scol,
                              const float* __restrict__ sval, const float2* __restrict__ Gu,
                              const float2* __restrict__ Gi, float2* __restrict__ y) {
  int row = blockIdx.x * 8 + (threadIdx.x >> 5);
  if (row >= NNODES) return;
  int lane = threadIdx.x & 31;
  int s = start[row], e = start[row + 1];
  GATHER4(__ldg(((c < NUSERS) ? Gu + (size_t)c * 32 : Gi + (size_t)(c - NUSERS) * 32) + lane))
  y[(size_t)row * 32 + lane] = make_float2(ax, ay);
}

// second cge pass fused with combine: cge = (ego + e1 + A@e1)/3
__global__ void spmm_csr_cge2(const int* __restrict__ start, const int* __restrict__ scol,
                              const float* __restrict__ sval, const float2* __restrict__ e1,
                              const float2* __restrict__ Gu, const float2* __restrict__ Gi,
                              float2* __restrict__ cge) {
  int row = blockIdx.x * 8 + (threadIdx.x >> 5);
  if (row >= NNODES) return;
  int lane = threadIdx.x & 31;
  int s = start[row], e = start[row + 1];
  GATHER4(__ldg(e1 + (size_t)c * 32 + lane))
  float2 ego = (row < NUSERS) ? __ldg(Gu + (size_t)row * 32 + lane)
                              : __ldg(Gi + (size_t)(row - NUSERS) * 32 + lane);
  float2 e1v = __ldg(e1 + (size_t)row * 32 + lane);
  cge[(size_t)row * 32 + lane] = make_float2((ego.x + e1v.x + ax) * (1.0f / 3.0f),
                                             (ego.y + e1v.y + ay) * (1.0f / 3.0f));
}

// mge adj pass, both modalities (blockIdx.y): gathers from (m0users*inv | itf)
__global__ void spmm_csr_mge_both(const int* __restrict__ start, const int* __restrict__ scol,
                                  const float* __restrict__ sval,
                                  const float2* __restrict__ m0A, const float2* __restrict__ m0B,
                                  const float2* __restrict__ itfA, const float2* __restrict__ itfB,
                                  const float* __restrict__ inv,
                                  float2* __restrict__ y0, float2* __restrict__ y1) {
  int row = blockIdx.x * 8 + (threadIdx.x >> 5);
  if (row >= NNODES) return;
  const float2* m0  = blockIdx.y ? m0B : m0A;
  const float2* itf = blockIdx.y ? itfB : itfA;
  float2* y = blockIdx.y ? y1 : y0;
  int lane = threadIdx.x & 31;
  int s = start[row], e = start[row + 1];
  GATHER4(((c < NUSERS)
            ? (v *= __ldg(inv + c), __ldg(m0 + (size_t)c * 32 + lane))
            : __ldg(itf + (size_t)(c - NUSERS) * 32 + lane)))
  y[(size_t)row * 32 + lane] = make_float2(ax, ay);
}

// r-spmm 64-col, both modalities (itf -> m0)
__global__ void spmm_csr64_both(const int* __restrict__ start, const int* __restrict__ scol,
                                const float* __restrict__ sval,
                                const float2* __restrict__ x0, const float2* __restrict__ x1,
                                float2* __restrict__ y0, float2* __restrict__ y1, int nrows) {
  int row = blockIdx.x * 8 + (threadIdx.x >> 5);
  if (row >= nrows) return;
  const float2* x = blockIdx.y ? x1 : x0;
  float2* y = blockIdx.y ? y1 : y0;
  int lane = threadIdx.x & 31;
  int s = start[row], e = start[row + 1];
  GATHER4(__ldg(x + (size_t)c * 32 + lane))
  y[(size_t)row * 32 + lane] = make_float2(ax, ay);
}

// r-spmm 32-col, both modalities (ihl -> uhl): lane holds 1 float
__global__ void spmm_csr32_both(const int* __restrict__ start, const int* __restrict__ scol,
                                const float* __restrict__ sval,
                                const float* __restrict__ x0, const float* __restrict__ x1,
                                float* __restrict__ y0, float* __restrict__ y1, int nrows) {
  int row = blockIdx.x * 8 + (threadIdx.x >> 5);
  if (row >= nrows) return;
  const float* x = blockIdx.y ? x1 : x0;
  float* y = blockIdx.y ? y1 : y0;
  int lane = threadIdx.x & 31;
  int s = start[row], e = start[row + 1];
  float a = 0.f;
  int i = s;
  for (; i + 3 < e; i += 4) {
    int c0 = __ldg(scol + i), c1 = __ldg(scol + i + 1);
    int c2 = __ldg(scol + i + 2), c3 = __ldg(scol + i + 3);
    float v0 = __ldg(sval + i), v1 = __ldg(sval + i + 1);
    float v2 = __ldg(sval + i + 2), v3 = __ldg(sval + i + 3);
    float x0v = __ldg(x + (size_t)c0 * 32 + lane);
    float x1v = __ldg(x + (size_t)c1 * 32 + lane);
    float x2v = __ldg(x + (size_t)c2 * 32 + lane);
    float x3v = __ldg(x + (size_t)c3 * 32 + lane);
    a = fmaf(v0, x0v, a); a = fmaf(v1, x1v, a);
    a = fmaf(v2, x2v, a); a = fmaf(v3, x3v, a);
  }
  for (; i < e; i++) {
    int c = __ldg(scol + i);
    a = fmaf(__ldg(sval + i), __ldg(x + (size_t)c * 32 + lane), a);
  }
  y[(size_t)row * 32 + lane] = a;
}

// ---------------- fused GEMM both modalities (round-6 version: measured best) ----------------
__global__ __launch_bounds__(256, 2)
void gemm_both_kernel(const float* __restrict__ A0, const float* __restrict__ A1,
                      const float* __restrict__ Bt0, const float* __restrict__ Bt1,
                      const float* __restrict__ Bh0, const float* __restrict__ Bh1,
                      float* __restrict__ Cf0, float* __restrict__ Cf1,
                      float* __restrict__ Cl0, float* __restrict__ Cl1,
                      int F0, int F1) {
  __shared__ float As[32][129];
  __shared__ float Bs[32][97];
  const int mmod = blockIdx.y;
  const float* A  = mmod ? A1 : A0;
  const float* Bt = mmod ? Bt1 : Bt0;
  const float* Bh = mmod ? Bh1 : Bh0;
  float* Cf = mmod ? Cf1 : Cf0;
  float* Cl = mmod ? Cl1 : Cl0;
  const int F = mmod ? F1 : F0;

  const int row0 = blockIdx.x * 128;
  const int tid = threadIdx.x;
  const int wid = tid >> 5, lane = tid & 31;
  const int wr = wid >> 1, wc = wid & 1;
  const int qid = lane >> 2, qtid = lane & 3;

  const int lr = tid >> 1;
  const int lk = (tid & 1) * 16;
  const int gr_l = row0 + lr;
  const bool rok = gr_l < NITEMS;
  const float* Arow = A + (size_t)gr_l * F + lk;

  float4 a4[4];
  float bb[12];
  const float4 z4 = make_float4(0.f, 0.f, 0.f, 0.f);
#pragma unroll
  for (int i = 0; i < 4; i++) a4[i] = rok ? __ldg((const float4*)(Arow + 4 * i)) : z4;
#pragma unroll
  for (int i = 0; i < 12; i++) {
    int idx = tid + 256 * i, kk = idx / 96, c = idx - kk * 96;
    bb[i] = (c < 64) ? __ldg(Bt + kk * 64 + c) : __ldg(Bh + kk * 32 + (c - 64));
  }

  float acc[2][6][4];
#pragma unroll
  for (int mt = 0; mt < 2; mt++)
#pragma unroll
    for (int nt = 0; nt < 6; nt++)
#pragma unroll
      for (int j = 0; j < 4; j++) acc[mt][nt][j] = 0.0f;

  for (int k0 = 0; k0 < F; k0 += 32) {
#pragma unroll
    for (int i = 0; i < 4; i++) {
      As[lk + 4 * i + 0][lr] = a4[i].x;
      As[lk + 4 * i + 1][lr] = a4[i].y;
      As[lk + 4 * i + 2][lr] = a4[i].z;
      As[lk + 4 * i + 3][lr] = a4[i].w;
    }
#pragma unroll
    for (int i = 0; i < 12; i++) {
      int idx = tid + 256 * i, kk = idx / 96, c = idx - kk * 96;
      Bs[kk][c] = bb[i];
    }
    __syncthreads();
    int kn = k0 + 32;
    if (kn < F) {
#pragma unroll
      for (int i = 0; i < 4; i++) a4[i] = rok ? __ldg((const float4*)(Arow + kn + 4 * i)) : z4;
#pragma unroll
      for (int i = 0; i < 12; i++) {
        int idx = tid + 256 * i, kk = idx / 96, c = idx - kk * 96;
        bb[i] = (c < 64) ? __ldg(Bt + (kn + kk) * 64 + c) : __ldg(Bh + (kn + kk) * 32 + (c - 64));
      }
    }
#pragma unroll
    for (int ks = 0; ks < 4; ks++) {
      const int kb = ks * 8;
      uint32_t ahi[2][4], alo[2][4];
#pragma unroll
      for (int mt = 0; mt < 2; mt++) {
        int ar = wr * 32 + mt * 16 + qid;
        tf32split(As[kb + qtid][ar],         ahi[mt][0], alo[mt][0]);
        tf32split(As[kb + qtid][ar + 8],     ahi[mt][1], alo[mt][1]);
        tf32split(As[kb + qtid + 4][ar],     ahi[mt][2], alo[mt][2]);
        tf32split(As[kb + qtid + 4][ar + 8], ahi[mt][3], alo[mt][3]);
      }
#pragma unroll
      for (int nt = 0; nt < 6; nt++) {
        int bn = wc * 48 + nt * 8 + qid;
        uint32_t bh[2], bl[2];
        tf32split(Bs[kb + qtid][bn],     bh[0], bl[0]);
        tf32split(Bs[kb + qtid + 4][bn], bh[1], bl[1]);
#pragma unroll
        for (int mt = 0; mt < 2; mt++) {
          mma8(acc[mt][nt], ahi[mt], bh);
          mma8(acc[mt][nt], ahi[mt], bl);
          mma8(acc[mt][nt], alo[mt], bh);
        }
      }
    }
    __syncthreads();
  }

#pragma unroll
  for (int mt = 0; mt < 2; mt++) {
    int gr = row0 + wr * 32 + mt * 16 + qid;
#pragma unroll
    for (int nt = 0; nt < 6; nt++) {
      int cc = wc * 48 + nt * 8 + 2 * qtid;
      if (gr < NITEMS) {
        if (cc < 64) { Cf[gr * 64 + cc] = acc[mt][nt][0]; Cf[gr * 64 + cc + 1] = acc[mt][nt][1]; }
        else         { Cl[gr * 32 + cc - 64] = acc[mt][nt][0]; Cl[gr * 32 + cc - 63] = acc[mt][nt][1]; }
      }
      if (gr + 8 < NITEMS) {
        if (cc < 64) { Cf[(gr + 8) * 64 + cc] = acc[mt][nt][2]; Cf[(gr + 8) * 64 + cc + 1] = acc[mt][nt][3]; }
        else         { Cl[(gr + 8) * 32 + cc - 64] = acc[mt][nt][2]; Cl[(gr + 8) * 32 + cc - 63] = acc[mt][nt][3]; }
      }
    }
  }
}

// ---------------- gumbel softmax both modalities, warp per row ----------------
__global__ void gumbel_both_kernel(const float* __restrict__ lg0, const float* __restrict__ lg1,
                                   float* __restrict__ o0, float* __restrict__ o1, int rows,
                                   unsigned k00, unsigned k01, unsigned k10, unsigned k11) {
  int row = blockIdx.x * 8 + (threadIdx.x >> 5);
  if (row >= rows) return;
  const float* logits = blockIdx.y ? lg1 : lg0;
  float* out = blockIdx.y ? o1 : o0;
  unsigned k0 = blockIdx.y ? k10 : k00;
  unsigned k1 = blockIdx.y ? k11 : k01;
  int lane = threadIdx.x & 31;
  unsigned idx = (unsigned)row * 32u + (unsigned)lane;
  unsigned b0, b1;
  tf2x32(k0, k1, 0u, idx, &b0, &b1);
  unsigned bits = b0 ^ b1;
  float f = __uint_as_float((bits >> 9) | 0x3f800000u) - 1.0f;
  const float TINY = 1.1754943508222875e-38f;
  float u = fmaxf(TINY, f + TINY);
  float g = -logf(-logf(u));
  float z = (logits[row * 32 + lane] + g) * 5.0f;
  float mx = z;
#pragma unroll
  for (int s = 16; s; s >>= 1) mx = fmaxf(mx, __shfl_xor_sync(0xffffffffu, mx, s));
  float e = expf(z - mx);
  float sm = e;
#pragma unroll
  for (int s = 16; s; s >>= 1) sm += __shfl_xor_sync(0xffffffffu, sm, s);
  out[row * 32 + lane] = e / sm;
}

// ---------------- lat[32,64] += ih^T @ icge, both modalities (lat pre-zeroed) ----------------
__global__ void lat_both_kernel(const float* __restrict__ w0, const float* __restrict__ w1,
                                const float* __restrict__ icge,
                                float* __restrict__ lat0, float* __restrict__ lat1, int chunk) {
  const float* w = blockIdx.y ? w1 : w0;
  float* lat = blockIdx.y ? lat1 : lat0;
  int lane = threadIdx.x & 31;
  int kg = threadIdx.x >> 5;
  int start = blockIdx.x * chunk;
  int end = min(start + chunk, NITEMS);
  float acc[8] = {0, 0, 0, 0, 0, 0, 0, 0};
  for (int it = start; it < end; ++it) {
    float wv = w[it * HH + lane];
    const float* cr = icge + it * EK + kg * 8;
#pragma unroll
    for (int j = 0; j < 8; j++) acc[j] = fmaf(wv, __ldg(cr + j), acc[j]);
  }
#pragma unroll
  for (int j = 0; j < 8; j++) atomicAdd(&lat[lane * EK + kg * 8 + j], acc[j]);
}

// ---------------- hyper apply, all 4 outputs in one launch ----------------
#define IBLK ((NITEMS * EK + 255) / 256)
#define UBLK ((NUSERS * EK + 255) / 256)
__global__ void hyper_apply_all(const float* __restrict__ ih0, const float* __restrict__ ih1,
                                const float* __restrict__ uh0, const float* __restrict__ uh1,
                                const float* __restrict__ lat0, const float* __restrict__ lat1,
                                float* __restrict__ outIV, float* __restrict__ outIT,
                                float* __restrict__ outUV, float* __restrict__ outUT) {
  __shared__ float sl[HH * EK];
  const float* lat = blockIdx.y ? lat1 : lat0;
  for (int t = threadIdx.x; t < HH * EK; t += 256) sl[t] = lat[t];
  __syncthreads();
  const float* w;
  float* out;
  int idx;
  if (blockIdx.x < IBLK) {
    w = blockIdx.y ? ih1 : ih0;
    out = blockIdx.y ? outIT : outIV;
    idx = blockIdx.x * 256 + threadIdx.x;
    if (idx >= NITEMS * EK) return;
  } else {
    w = blockIdx.y ? uh1 : uh0;
    out = blockIdx.y ? outUT : outUV;
    idx = (blockIdx.x - IBLK) * 256 + threadIdx.x;
    if (idx >= NUSERS * EK) return;
  }
  int r = idx >> 6, k = idx & 63;
  float s = 0.0f;
#pragma unroll
  for (int h = 0; h < HH; h++) s = fmaf(w[r * HH + h], sl[h * EK + k], s);
  out[idx] = s;
}

// ---------------- final ----------------
__global__ void final_kernel(float* __restrict__ out, const float* __restrict__ cge,
                             const float* __restrict__ m1a, const float* __restrict__ m1b) {
  const int OI   = NUSERS * EK;
  const int OHVU = (NUSERS + NITEMS) * EK;
  const int OHVI = OHVU + NUSERS * EK;
  const int OHTU = OHVI + NITEMS * EK;
  const int OHTI = OHTU + NUSERS * EK;
  int row = blockIdx.x * 8 + (threadIdx.x >> 5);
  if (row >= NNODES) return;
  int lane = threadIdx.x & 31;
  const float* hv;
  const float* ht;
  float* dst;
  if (row < NUSERS) {
    hv = out + OHVU + row * EK; ht = out + OHTU + row * EK; dst = out + row * EK;
  } else {
    int ir = row - NUSERS;
    hv = out + OHVI + ir * EK;  ht = out + OHTI + ir * EK;  dst = out + OI + ir * EK;
  }
  int b = row * EK;
  float a0 = m1a[b + lane], a1 = m1a[b + lane + 32];
  float c0 = m1b[b + lane], c1 = m1b[b + lane + 32];
  float g0 = hv[lane] + ht[lane];
  float g1 = hv[lane + 32] + ht[lane + 32];
  float sa = a0 * a0 + a1 * a1;
  float sc = c0 * c0 + c1 * c1;
  float sg = g0 * g0 + g1 * g1;
#pragma unroll
  for (int s = 16; s; s >>= 1) {
    sa += __shfl_xor_sync(0xffffffffu, sa, s);
    sc += __shfl_xor_sync(0xffffffffu, sc, s);
    sg += __shfl_xor_sync(0xffffffffu, sg, s);
  }
  float ia = 1.0f / fmaxf(sqrtf(sa), 1e-12f);
  float ic = 1.0f / fmaxf(sqrtf(sc), 1e-12f);
  float ig = 0.2f / fmaxf(sqrtf(sg), 1e-12f);
  dst[lane]      = cge[b + lane]      + a0 * ia + c0 * ic + g0 * ig;
  dst[lane + 32] = cge[b + lane + 32] + a1 * ia + c1 * ic + g1 * ig;
}

// ================================================================================
extern "C" void kernel_launch(void* const* d_in, const int* in_sizes, int n_in,
                              void* d_out, int out_size) {
  const float* Gu       = (const float*)d_in[0];
  const float* Gi       = (const float*)d_in[1];
  const float* feat_v   = (const float*)d_in[2];
  const float* feat_t   = (const float*)d_in[3];
  const float* trs_v    = (const float*)d_in[4];
  const float* trs_t    = (const float*)d_in[5];
  const float* hyp_v    = (const float*)d_in[6];
  const float* hyp_t    = (const float*)d_in[7];
  const float* inv      = (const float*)d_in[8];
  const float* adj_vals = (const float*)d_in[9];
  const float* r_vals   = (const float*)d_in[10];
  const int*   adj_rows = (const int*)d_in[11];
  const int*   adj_cols = (const int*)d_in[12];
  const int*   r_rows   = (const int*)d_in[13];
  const int*   r_cols   = (const int*)d_in[14];
  float* out = (float*)d_out;
  int Fv = in_sizes[2] / NITEMS;
  int Ft = in_sizes[3] / NITEMS;

  float *p_itf, *p_ihl, *p_uhl, *p_ih, *p_uh, *p_e0, *p_e1, *p_m0, *p_m1, *p_lat;
  int *pA_start, *pA_cur, *pA_scol, *pA_csum, *pA_coff;
  int *pR_start, *pR_cur, *pR_scol, *pR_csum, *pR_coff;
  float *pA_sval, *pR_sval;
  cudaGetSymbolAddress((void**)&p_itf, g_itf);
  cudaGetSymbolAddress((void**)&p_ihl, g_ihl);
  cudaGetSymbolAddress((void**)&p_uhl, g_uhl);
  cudaGetSymbolAddress((void**)&p_ih,  g_ih);
  cudaGetSymbolAddress((void**)&p_uh,  g_uh);
  cudaGetSymbolAddress((void**)&p_e0,  g_e0);
  cudaGetSymbolAddress((void**)&p_e1,  g_e1);
  cudaGetSymbolAddress((void**)&p_m0,  g_m0);
  cudaGetSymbolAddress((void**)&p_m1,  g_m1);
  cudaGetSymbolAddress((void**)&p_lat, g_lat);
  cudaGetSymbolAddress((void**)&pA_start, g_startA);
  cudaGetSymbolAddress((void**)&pA_cur,   g_curA);
  cudaGetSymbolAddress((void**)&pA_scol,  g_scolA);
  cudaGetSymbolAddress((void**)&pA_sval,  g_svalA);
  cudaGetSymbolAddress((void**)&pA_csum,  g_csumA);
  cudaGetSymbolAddress((void**)&pA_coff,  g_coffA);
  cudaGetSymbolAddress((void**)&pR_start, g_startR);
  cudaGetSymbolAddress((void**)&pR_cur,   g_curR);
  cudaGetSymbolAddress((void**)&pR_scol,  g_scolR);
  cudaGetSymbolAddress((void**)&pR_sval,  g_svalR);
  cudaGetSymbolAddress((void**)&pR_csum,  g_csumR);
  cudaGetSymbolAddress((void**)&pR_coff,  g_coffR);
  float* p_itfT = p_itf + NITEMS * EK;
  float* p_ihlT = p_ihl + NITEMS * HH;
  float* p_uhlT = p_uhl + NUSERS * HH;
  float* p_ihT  = p_ih + NITEMS * HH;
  float* p_uhT  = p_uh + NUSERS * HH;
  float* p_m0T  = p_m0 + NUSERS * EK;
  float* p_m1T  = p_m1 + NNODES * EK;
  float* p_latT = p_lat + HH * EK;

  // JAX threefry keys
  uint32_t ki0[2], ki1[2], ku0[2], ku1[2];
  for (int m = 0; m < 2; m++) {
    uint32_t km0, km1;
    tf2x32(0u, 42u, 0u, (uint32_t)m, &km0, &km1);
    tf2x32(km0, km1, 0u, 0u, &ki0[m], &ki1[m]);
    tf2x32(km0, km1, 0u, 1u, &ku0[m], &ku1[m]);
  }

  const int GADJE = (NNZADJ + 255) / 256;
  const int GRE   = (NNZR + 255) / 256;
  const int GNODE = (NNODES + 7) / 8;
  const int GUSER = (NUSERS + 7) / 8;
  const int OHVU = (NUSERS + NITEMS) * EK;
  const int OHVI = OHVU + NUSERS * EK;
  const int OHTU = OHVI + NITEMS * EK;
  const int OHTI = OHTU + NUSERS * EK;

  // ---- zero CSR histograms + lat ----
  cudaMemsetAsync(pA_start, 0, (NNODES + 1) * sizeof(int), 0);
  cudaMemsetAsync(pR_start, 0, (NUSERS + 1) * sizeof(int), 0);
  cudaMemsetAsync(p_lat, 0, 2 * HH * EK * sizeof(float), 0);

  // ---- both GEMMs ----
  gemm_both_kernel<<<dim3((NITEMS + 127) / 128, 2), 256>>>(
      feat_v, feat_t, trs_v, trs_t, hyp_v, hyp_t,
      p_itf, p_itfT, p_ihl, p_ihlT, Fv, Ft);

  // ---- CSR builds (adj + r), merged launches ----
  csr_hist2<<<GADJE + GRE, 256>>>(adj_rows, r_rows, NNZADJ, NNZR, GADJE, pA_start, pR_start);
  csr_chunksum2<<<NCHA + NCHR, 256>>>(pA_start, pR_start, pA_csum, pR_csum, NNODES, NUSERS);
  csr_scanchunks2<<<2, 32>>>(pA_csum, pA_coff, pA_start, pR_csum, pR_coff, pR_start);
  csr_chunkscan2<<<NCHA + NCHR, 256>>>(pA_start, pA_coff, pA_cur,
                                       pR_start, pR_coff, pR_cur, NNODES, NUSERS);
  csr_scatter2<<<GADJE + GRE, 256>>>(adj_rows, adj_cols, adj_vals, pA_cur, pA_scol, pA_sval,
                                     r_rows, r_cols, r_vals, pR_cur, pR_scol, pR_sval,
                                     NNZADJ, NNZR, GADJE);

  // ---- cge chain (gather, combine fused into pass 2) ----
  spmm_csr_cge1<<<GNODE, 256>>>(pA_start, pA_scol, pA_sval,
                                (const float2*)Gu, (const float2*)Gi, (float2*)p_e1);
  spmm_csr_cge2<<<GNODE, 256>>>(pA_start, pA_scol, pA_sval, (const float2*)p_e1,
                                (const float2*)Gu, (const float2*)Gi, (float2*)p_e0);

  // ---- gumbel (items) ----
  gumbel_both_kernel<<<dim3((NITEMS + 7) / 8, 2), 256>>>(
      p_ihl, p_ihlT, p_ih, p_ihT, NITEMS, ki0[0], ki1[0], ki0[1], ki1[1]);

  // ---- r-spmms (gather) ----
  spmm_csr32_both<<<dim3(GUSER, 2), 256>>>(pR_start, pR_scol, pR_sval,
                                           p_ihl, p_ihlT, p_uhl, p_uhlT, NUSERS);
  gumbel_both_kernel<<<dim3(GUSER, 2), 256>>>(
      p_uhl, p_uhlT, p_uh, p_uhT, NUSERS, ku0[0], ku1[0], ku0[1], ku1[1]);
  spmm_csr64_both<<<dim3(GUSER, 2), 256>>>(pR_start, pR_scol, pR_sval,
                                           (const float2*)p_itf, (const float2*)p_itfT,
                                           (float2*)p_m0, (float2*)p_m0T, NUSERS);

  // ---- mge adj pass (gather) ----
  spmm_csr_mge_both<<<dim3(GNODE, 2), 256>>>(pA_start, pA_scol, pA_sval,
                                             (const float2*)p_m0, (const float2*)p_m0T,
                                             (const float2*)p_itf, (const float2*)p_itfT,
                                             inv, (float2*)p_m1, (float2*)p_m1T);

  // ---- hyper path ----
  lat_both_kernel<<<dim3(120, 2), 256>>>(p_ih, p_ihT, p_e0 + NUSERS * EK, p_lat, p_latT, 250);
  hyper_apply_all<<<dim3(IBLK + UBLK, 2), 256>>>(
      p_ih, p_ihT, p_uh, p_uhT, p_lat, p_latT,
      out + OHVI, out + OHTI, out + OHVU, out + OHTU);

  final_kernel<<<GNODE, 256>>>(out, p_e0, p_m1, p_m1T);
}

// round 10
// speedup vs baseline: 1.6623x; 1.3117x over previous
#include <cuda_runtime.h>
#include <stdint.h>

#define NUSERS 50000
#define NITEMS 30000
#define NNODES 80000
#define EK 64
#define HH 32
#define NNZADJ 2000000
#define NNZR 1000000
#define NCHA ((NNODES + 1023) / 1024)
#define NCHR ((NUSERS + 1023) / 1024)

// ---------------- scratch (device globals; allocation is forbidden) ----------------
__device__ float g_itf[2][NITEMS * EK];
__device__ float g_ihl[2][NITEMS * HH];
__device__ float g_uhl[2][NUSERS * HH];
__device__ float g_ih[2][NITEMS * HH];
__device__ float g_uh[2][NUSERS * HH];
__device__ float g_e0[NNODES * EK];      // cge
__device__ float g_e1[NNODES * EK];
__device__ float g_m0[2][NUSERS * EK];
__device__ float g_m1[2][NNODES * EK];
__device__ float g_lat[2][HH * EK];
// CSR scratch (histA and histR in ONE buffer so one memset clears both)
__device__ int   g_hist[NNODES + 1 + NUSERS + 1];
__device__ int   g_curA[NNODES];
__device__ int   g_scolA[NNZADJ];
__device__ float g_svalA[NNZADJ];
__device__ int   g_csumA[NCHA];
__device__ int   g_coffA[NCHA];
__device__ int   g_curR[NUSERS];
__device__ int   g_scolR[NNZR];
__device__ float g_svalR[NNZR];
__device__ int   g_csumR[NCHR];
__device__ int   g_coffR[NCHR];

// ---------------- threefry2x32 (JAX-compatible, 20 rounds) ----------------
__host__ __device__ __forceinline__ void tf2x32(uint32_t k0, uint32_t k1,
                                                uint32_t x0, uint32_t x1,
                                                uint32_t* o0, uint32_t* o1) {
  uint32_t ks2 = k0 ^ k1 ^ 0x1BD11BDAu;
  uint32_t v0 = x0 + k0, v1 = x1 + k1;
#define TFR(r) { v0 += v1; v1 = (v1 << (r)) | (v1 >> (32 - (r))); v1 ^= v0; }
  TFR(13) TFR(15) TFR(26) TFR(6)
  v0 += k1;  v1 += ks2 + 1u;
  TFR(17) TFR(29) TFR(16) TFR(24)
  v0 += ks2; v1 += k0 + 2u;
  TFR(13) TFR(15) TFR(26) TFR(6)
  v0 += k0;  v1 += k1 + 3u;
  TFR(17) TFR(29) TFR(16) TFR(24)
  v0 += k1;  v1 += ks2 + 4u;
  TFR(13) TFR(15) TFR(26) TFR(6)
  v0 += ks2; v1 += k0 + 5u;
#undef TFR
  *o0 = v0; *o1 = v1;
}

// ---------------- bf16 split + mma helpers ----------------
// pack {bf16(x0) lo-half, bf16(x1) hi-half} plus the bf16 residuals
__device__ __forceinline__ uint2 bf16split2(float x0, float x1) {
  uint32_t h;
  asm("cvt.rn.bf16x2.f32 %0, %1, %2;" : "=r"(h) : "f"(x1), "f"(x0));
  float h0 = __uint_as_float(h << 16);
  float h1 = __uint_as_float(h & 0xFFFF0000u);
  uint32_t l;
  asm("cvt.rn.bf16x2.f32 %0, %1, %2;" : "=r"(l) : "f"(x1 - h1), "f"(x0 - h0));
  return make_uint2(h, l);
}

__device__ __forceinline__ void mma16(float* c, const uint32_t* a, const uint32_t* b) {
  asm volatile("mma.sync.aligned.m16n8k16.row.col.f32.bf16.bf16.f32 "
               "{%0,%1,%2,%3}, {%4,%5,%6,%7}, {%8,%9}, {%0,%1,%2,%3};"
               : "+f"(c[0]), "+f"(c[1]), "+f"(c[2]), "+f"(c[3])
               : "r"(a[0]), "r"(a[1]), "r"(a[2]), "r"(a[3]), "r"(b[0]), "r"(b[1]));
}

// ================= CSR build (counting sort by row), merged A+R launches =================
__global__ void csr_hist2(const int* __restrict__ rowsA, const int* __restrict__ rowsB,
                          int nnzA, int nnzB, int gA,
                          int* __restrict__ cntA, int* __restrict__ cntB) {
  int b = blockIdx.x;
  if (b < gA) {
    int e = b * 256 + threadIdx.x;
    if (e < nnzA) atomicAdd(&cntA[__ldg(rowsA + e)], 1);
  } else {
    int e = (b - gA) * 256 + threadIdx.x;
    if (e < nnzB) atomicAdd(&cntB[__ldg(rowsB + e)], 1);
  }
}

__global__ void csr_chunksum2(const int* __restrict__ cntA, const int* __restrict__ cntB,
                              int* __restrict__ csumA, int* __restrict__ csumB,
                              int nA, int nB) {
  __shared__ int ts[256];
  const int* cnt;
  int* csum;
  int n, ch;
  if (blockIdx.x < NCHA) { cnt = cntA; csum = csumA; n = nA; ch = blockIdx.x; }
  else                   { cnt = cntB; csum = csumB; n = nB; ch = blockIdx.x - NCHA; }
  int base = ch * 1024;
  int s = 0;
  for (int i = threadIdx.x; i < 1024; i += 256) {
    int idx = base + i;
    s += (idx < n) ? cnt[idx] : 0;
  }
  ts[threadIdx.x] = s;
  __syncthreads();
  for (int off = 128; off; off >>= 1) {
    if (threadIdx.x < off) ts[threadIdx.x] += ts[threadIdx.x + off];
    __syncthreads();
  }
  if (threadIdx.x == 0) csum[ch] = ts[0];
}

__global__ void csr_scanchunks2(const int* __restrict__ csumA, int* __restrict__ coffA,
                                int* __restrict__ startA,
                                const int* __restrict__ csumB, int* __restrict__ coffB,
                                int* __restrict__ startB) {
  if (threadIdx.x != 0) return;
  if (blockIdx.x == 0) {
    int run = 0;
    for (int i = 0; i < NCHA; i++) { coffA[i] = run; run += csumA[i]; }
    startA[NNODES] = NNZADJ;
  } else {
    int run = 0;
    for (int i = 0; i < NCHR; i++) { coffB[i] = run; run += csumB[i]; }
    startB[NUSERS] = NNZR;
  }
}

__global__ void csr_chunkscan2(int* __restrict__ cntA, const int* __restrict__ coffA,
                               int* __restrict__ curA,
                               int* __restrict__ cntB, const int* __restrict__ coffB,
                               int* __restrict__ curB, int nA, int nB) {
  __shared__ int sm[1024];
  __shared__ int ts[256];
  int* cnt;
  const int* coff;
  int* cur;
  int n, ch;
  if (blockIdx.x < NCHA) { cnt = cntA; coff = coffA; cur = curA; n = nA; ch = blockIdx.x; }
  else                   { cnt = cntB; coff = coffB; cur = curB; n = nB; ch = blockIdx.x - NCHA; }
  int base = ch * 1024;
  for (int i = threadIdx.x; i < 1024; i += 256)
    sm[i] = (base + i < n) ? cnt[base + i] : 0;
  __syncthreads();
  int t = threadIdx.x;
  int a0 = sm[t * 4], a1 = sm[t * 4 + 1], a2 = sm[t * 4 + 2], a3 = sm[t * 4 + 3];
  int local = a0 + a1 + a2 + a3;
  ts[t] = local;
  __syncthreads();
  for (int off = 1; off < 256; off <<= 1) {
    int v = (t >= off) ? ts[t - off] : 0;
    __syncthreads();
    ts[t] += v;
    __syncthreads();
  }
  int excl = ts[t] - local + coff[ch];
  int i0 = base + t * 4;
  if (i0 + 0 < n) { cnt[i0 + 0] = excl;                cur[i0 + 0] = excl; }
  if (i0 + 1 < n) { cnt[i0 + 1] = excl + a0;           cur[i0 + 1] = excl + a0; }
  if (i0 + 2 < n) { cnt[i0 + 2] = excl + a0 + a1;      cur[i0 + 2] = excl + a0 + a1; }
  if (i0 + 3 < n) { cnt[i0 + 3] = excl + a0 + a1 + a2; cur[i0 + 3] = excl + a0 + a1 + a2; }
}

__global__ void csr_scatter2(const int* __restrict__ rowsA, const int* __restrict__ colsA,
                             const float* __restrict__ valsA, int* __restrict__ curA,
                             int* __restrict__ scolA, float* __restrict__ svalA,
                             const int* __restrict__ rowsB, const int* __restrict__ colsB,
                             const float* __restrict__ valsB, int* __restrict__ curB,
                             int* __restrict__ scolB, float* __restrict__ svalB,
                             int nnzA, int nnzB, int gA) {
  int b = blockIdx.x;
  if (b < gA) {
    int e = b * 256 + threadIdx.x;
    if (e >= nnzA) return;
    int r = __ldg(rowsA + e);
    int p = atomicAdd(&curA[r], 1);
    scolA[p] = __ldg(colsA + e);
    svalA[p] = __ldg(valsA + e);
  } else {
    int e = (b - gA) * 256 + threadIdx.x;
    if (e >= nnzB) return;
    int r = __ldg(rowsB + e);
    int p = atomicAdd(&curB[r], 1);
    scolB[p] = __ldg(colsB + e);
    svalB[p] = __ldg(valsB + e);
  }
}

// ================= CSR gather SpMMs (warp per row, 4x unrolled, no atomics) =================
#define GATHER4(XEXPR)                                                        \
  float ax = 0.f, ay = 0.f;                                                   \
  int i = s;                                                                  \
  for (; i + 3 < e; i += 4) {                                                 \
    int c0 = __ldg(scol + i), c1 = __ldg(scol + i + 1);                       \
    int c2 = __ldg(scol + i + 2), c3 = __ldg(scol + i + 3);                   \
    float v0 = __ldg(sval + i), v1 = __ldg(sval + i + 1);                     \
    float v2 = __ldg(sval + i + 2), v3 = __ldg(sval + i + 3);                 \
    float2 x0, x1, x2, x3;                                                    \
    { int c = c0; float& v = v0; x0 = (XEXPR); (void)v; }                     \
    { int c = c1; float& v = v1; x1 = (XEXPR); (void)v; }                     \
    { int c = c2; float& v = v2; x2 = (XEXPR); (void)v; }                     \
    { int c = c3; float& v = v3; x3 = (XEXPR); (void)v; }                     \
    ax = fmaf(v0, x0.x, ax); ay = fmaf(v0, x0.y, ay);                         \
    ax = fmaf(v1, x1.x, ax); ay = fmaf(v1, x1.y, ay);                         \
    ax = fmaf(v2, x2.x, ax); ay = fmaf(v2, x2.y, ay);                         \
    ax = fmaf(v3, x3.x, ax); ay = fmaf(v3, x3.y, ay);                         \
  }                                                                           \
  for (; i < e; i++) {                                                        \
    int c = __ldg(scol + i);                                                  \
    float v = __ldg(sval + i);                                                \
    float2 xv = (XEXPR);                                                      \
    ax = fmaf(v, xv.x, ax); ay = fmaf(v, xv.y, ay);                           \
  }

// first cge pass: x = concat(Gu, Gi)
__global__ void spmm_csr_cge1(const int* __restrict__ start, const int* __restrict__ scol,
                              const float* __restrict__ sval, const float2* __restrict__ Gu,
                              const float2* __restrict__ Gi, float2* __restrict__ y) {
  int row = blockIdx.x * 8 + (threadIdx.x >> 5);
  if (row >= NNODES) return;
  int lane = threadIdx.x & 31;
  int s = start[row], e = start[row + 1];
  GATHER4(__ldg(((c < NUSERS) ? Gu + (size_t)c * 32 : Gi + (size_t)(c - NUSERS) * 32) + lane))
  y[(size_t)row * 32 + lane] = make_float2(ax, ay);
}

// second cge pass fused with combine: cge = (ego + e1 + A@e1)/3
__global__ void spmm_csr_cge2(const int* __restrict__ start, const int* __restrict__ scol,
                              const float* __restrict__ sval, const float2* __restrict__ e1,
                              const float2* __restrict__ Gu, const float2* __restrict__ Gi,
                              float2* __restrict__ cge) {
  int row = blockIdx.x * 8 + (threadIdx.x >> 5);
  if (row >= NNODES) return;
  int lane = threadIdx.x & 31;
  int s = start[row], e = start[row + 1];
  GATHER4(__ldg(e1 + (size_t)c * 32 + lane))
  float2 ego = (row < NUSERS) ? __ldg(Gu + (size_t)row * 32 + lane)
                              : __ldg(Gi + (size_t)(row - NUSERS) * 32 + lane);
  float2 e1v = __ldg(e1 + (size_t)row * 32 + lane);
  cge[(size_t)row * 32 + lane] = make_float2((ego.x + e1v.x + ax) * (1.0f / 3.0f),
                                             (ego.y + e1v.y + ay) * (1.0f / 3.0f));
}

// mge adj pass, both modalities (blockIdx.y): gathers from (m0users*inv | itf)
__global__ void spmm_csr_mge_both(const int* __restrict__ start, const int* __restrict__ scol,
                                  const float* __restrict__ sval,
                                  const float2* __restrict__ m0A, const float2* __restrict__ m0B,
                                  const float2* __restrict__ itfA, const float2* __restrict__ itfB,
                                  const float* __restrict__ inv,
                                  float2* __restrict__ y0, float2* __restrict__ y1) {
  int row = blockIdx.x * 8 + (threadIdx.x >> 5);
  if (row >= NNODES) return;
  const float2* m0  = blockIdx.y ? m0B : m0A;
  const float2* itf = blockIdx.y ? itfB : itfA;
  float2* y = blockIdx.y ? y1 : y0;
  int lane = threadIdx.x & 31;
  int s = start[row], e = start[row + 1];
  GATHER4(((c < NUSERS)
            ? (v *= __ldg(inv + c), __ldg(m0 + (size_t)c * 32 + lane))
            : __ldg(itf + (size_t)(c - NUSERS) * 32 + lane)))
  y[(size_t)row * 32 + lane] = make_float2(ax, ay);
}

// fused r-spmm: one CSR-R read feeds BOTH gathers (ihl[32]->uhl and itf[64]->m0)
__global__ void spmm_r_fused(const int* __restrict__ start, const int* __restrict__ scol,
                             const float* __restrict__ sval,
                             const float* __restrict__ xs0, const float* __restrict__ xs1,
                             const float2* __restrict__ xd0, const float2* __restrict__ xd1,
                             float* __restrict__ ys0, float* __restrict__ ys1,
                             float2* __restrict__ yd0, float2* __restrict__ yd1) {
  int row = blockIdx.x * 8 + (threadIdx.x >> 5);
  if (row >= NUSERS) return;
  const float* xs = blockIdx.y ? xs1 : xs0;
  const float2* xd = blockIdx.y ? xd1 : xd0;
  float* ys = blockIdx.y ? ys1 : ys0;
  float2* yd = blockIdx.y ? yd1 : yd0;
  int lane = threadIdx.x & 31;
  int s = start[row], e = start[row + 1];
  float a = 0.f, ax = 0.f, ay = 0.f;
  int i = s;
  for (; i + 1 < e; i += 2) {
    int c0 = __ldg(scol + i), c1 = __ldg(scol + i + 1);
    float v0 = __ldg(sval + i), v1 = __ldg(sval + i + 1);
    float s0 = __ldg(xs + (size_t)c0 * 32 + lane);
    float s1 = __ldg(xs + (size_t)c1 * 32 + lane);
    float2 d0 = __ldg(xd + (size_t)c0 * 32 + lane);
    float2 d1 = __ldg(xd + (size_t)c1 * 32 + lane);
    a = fmaf(v0, s0, a); ax = fmaf(v0, d0.x, ax); ay = fmaf(v0, d0.y, ay);
    a = fmaf(v1, s1, a); ax = fmaf(v1, d1.x, ax); ay = fmaf(v1, d1.y, ay);
  }
  for (; i < e; i++) {
    int c = __ldg(scol + i);
    float v = __ldg(sval + i);
    a = fmaf(v, __ldg(xs + (size_t)c * 32 + lane), a);
    float2 d = __ldg(xd + (size_t)c * 32 + lane);
    ax = fmaf(v, d.x, ax); ay = fmaf(v, d.y, ay);
  }
  ys[(size_t)row * 32 + lane] = a;
  yd[(size_t)row * 32 + lane] = make_float2(ax, ay);
}

// ---------------- fused GEMM both modalities: bf16x3 tensor-core path ----------------
// blockIdx.y: 0 = visual, 1 = text. Cf = A@Bt [64 cols], Cl = A@Bh [32 cols].
// Block 128x96, 8 warps as 4(row)x2(col); warp tile 32x48 = 2 m16 x 6 n8, k16 per mma.
// smem holds {hi,lo} bf16x2 pairs, pair index k2 = k/2.
#define ASP 132
#define BSP 100
__global__ __launch_bounds__(256, 2)
void gemm_both_kernel(const float* __restrict__ A0, const float* __restrict__ A1,
                      const float* __restrict__ Bt0, const float* __restrict__ Bt1,
                      const float* __restrict__ Bh0, const float* __restrict__ Bh1,
                      float* __restrict__ Cf0, float* __restrict__ Cf1,
                      float* __restrict__ Cl0, float* __restrict__ Cl1,
                      int F0, int F1) {
  __shared__ uint2 AsP[16][ASP];
  __shared__ uint2 BsP[16][BSP];
  const int mmod = blockIdx.y;
  const float* A  = mmod ? A1 : A0;
  const float* Bt = mmod ? Bt1 : Bt0;
  const float* Bh = mmod ? Bh1 : Bh0;
  float* Cf = mmod ? Cf1 : Cf0;
  float* Cl = mmod ? Cl1 : Cl0;
  const int F = mmod ? F1 : F0;

  const int row0 = blockIdx.x * 128;
  const int tid = threadIdx.x;
  const int wid = tid >> 5, lane = tid & 31;
  const int wr = wid >> 1, wc = wid & 1;
  const int qid = lane >> 2, qtid = lane & 3;

  const int lr = tid >> 1;            // load row 0..127
  const int lk2 = (tid & 1) * 8;      // k2 offset (k offset 0 or 16)
  const int gr_l = row0 + lr;
  const bool rok = gr_l < NITEMS;
  const float* Arow = A + (size_t)gr_l * F + lk2 * 2;

  float4 a4[4];
  float bb0[6], bb1[6];
  const float4 z4 = make_float4(0.f, 0.f, 0.f, 0.f);
#pragma unroll
  for (int i = 0; i < 4; i++) a4[i] = rok ? __ldg((const float4*)(Arow + 4 * i)) : z4;
#pragma unroll
  for (int i = 0; i < 6; i++) {
    int p = tid + 256 * i, k2 = p / 96, c = p - k2 * 96;
    int kk = 2 * k2;
    if (c < 64) { bb0[i] = __ldg(Bt + kk * 64 + c); bb1[i] = __ldg(Bt + (kk + 1) * 64 + c); }
    else        { bb0[i] = __ldg(Bh + kk * 32 + c - 64); bb1[i] = __ldg(Bh + (kk + 1) * 32 + c - 64); }
  }

  float acc[2][6][4];
#pragma unroll
  for (int mt = 0; mt < 2; mt++)
#pragma unroll
    for (int nt = 0; nt < 6; nt++)
#pragma unroll
      for (int j = 0; j < 4; j++) acc[mt][nt][j] = 0.0f;

  for (int k0 = 0; k0 < F; k0 += 32) {
    // stage + split once per element
    float av[16];
#pragma unroll
    for (int i = 0; i < 4; i++) {
      av[4 * i + 0] = a4[i].x; av[4 * i + 1] = a4[i].y;
      av[4 * i + 2] = a4[i].z; av[4 * i + 3] = a4[i].w;
    }
#pragma unroll
    for (int j = 0; j < 8; j++)
      AsP[lk2 + j][lr] = bf16split2(av[2 * j], av[2 * j + 1]);
#pragma unroll
    for (int i = 0; i < 6; i++) {
      int p = tid + 256 * i, k2 = p / 96, c = p - k2 * 96;
      BsP[k2][c] = bf16split2(bb0[i], bb1[i]);
    }
    __syncthreads();
    int kn = k0 + 32;
    if (kn < F) {
#pragma unroll
      for (int i = 0; i < 4; i++) a4[i] = rok ? __ldg((const float4*)(Arow + kn + 4 * i)) : z4;
#pragma unroll
      for (int i = 0; i < 6; i++) {
        int p = tid + 256 * i, k2 = p / 96, c = p - k2 * 96;
        int kk = kn + 2 * k2;
        if (c < 64) { bb0[i] = __ldg(Bt + kk * 64 + c); bb1[i] = __ldg(Bt + (kk + 1) * 64 + c); }
        else        { bb0[i] = __ldg(Bh + kk * 32 + c - 64); bb1[i] = __ldg(Bh + (kk + 1) * 32 + c - 64); }
      }
    }
#pragma unroll
    for (int ks = 0; ks < 2; ks++) {
      const int kb = ks * 8;
      uint2 a2[2][4];
#pragma unroll
      for (int mt = 0; mt < 2; mt++) {
        int ar = wr * 32 + mt * 16 + qid;
        a2[mt][0] = AsP[kb + qtid][ar];
        a2[mt][1] = AsP[kb + qtid][ar + 8];
        a2[mt][2] = AsP[kb + qtid + 4][ar];
        a2[mt][3] = AsP[kb + qtid + 4][ar + 8];
      }
#pragma unroll
      for (int nt = 0; nt < 6; nt++) {
        int bn = wc * 48 + nt * 8 + qid;
        uint2 b0 = BsP[kb + qtid][bn];
        uint2 b1 = BsP[kb + qtid + 4][bn];
        uint32_t bhv[2] = {b0.x, b1.x};
        uint32_t blv[2] = {b0.y, b1.y};
#pragma unroll
        for (int mt = 0; mt < 2; mt++) {
          uint32_t ah[4] = {a2[mt][0].x, a2[mt][1].x, a2[mt][2].x, a2[mt][3].x};
          uint32_t al[4] = {a2[mt][0].y, a2[mt][1].y, a2[mt][2].y, a2[mt][3].y};
          mma16(acc[mt][nt], ah, bhv);
          mma16(acc[mt][nt], ah, blv);
          mma16(acc[mt][nt], al, bhv);
        }
      }
    }
    __syncthreads();
  }

  // epilogue: c0,c1 at row qid; c2,c3 at row qid+8; cols 2*qtid, 2*qtid+1
#pragma unroll
  for (int mt = 0; mt < 2; mt++) {
    int gr = row0 + wr * 32 + mt * 16 + qid;
#pragma unroll
    for (int nt = 0; nt < 6; nt++) {
      int cc = wc * 48 + nt * 8 + 2 * qtid;
      if (gr < NITEMS) {
        if (cc < 64) { Cf[gr * 64 + cc] = acc[mt][nt][0]; Cf[gr * 64 + cc + 1] = acc[mt][nt][1]; }
        else         { Cl[gr * 32 + cc - 64] = acc[mt][nt][0]; Cl[gr * 32 + cc - 63] = acc[mt][nt][1]; }
      }
      if (gr + 8 < NITEMS) {
        if (cc < 64) { Cf[(gr + 8) * 64 + cc] = acc[mt][nt][2]; Cf[(gr + 8) * 64 + cc + 1] = acc[mt][nt][3]; }
        else         { Cl[(gr + 8) * 32 + cc - 64] = acc[mt][nt][2]; Cl[(gr + 8) * 32 + cc - 63] = acc[mt][nt][3]; }
      }
    }
  }
}

// ---------------- gumbel softmax both modalities, warp per row ----------------
__global__ void gumbel_both_kernel(const float* __restrict__ lg0, const float* __restrict__ lg1,
                                   float* __restrict__ o0, float* __restrict__ o1, int rows,
                                   unsigned k00, unsigned k01, unsigned k10, unsigned k11) {
  int row = blockIdx.x * 8 + (threadIdx.x >> 5);
  if (row >= rows) return;
  const float* logits = blockIdx.y ? lg1 : lg0;
  float* out = blockIdx.y ? o1 : o0;
  unsigned k0 = blockIdx.y ? k10 : k00;
  unsigned k1 = blockIdx.y ? k11 : k01;
  int lane = threadIdx.x & 31;
  unsigned idx = (unsigned)row * 32u + (unsigned)lane;
  unsigned b0, b1;
  tf2x32(k0, k1, 0u, idx, &b0, &b1);
  unsigned bits = b0 ^ b1;
  float f = __uint_as_float((bits >> 9) | 0x3f800000u) - 1.0f;
  const float TINY = 1.1754943508222875e-38f;
  float u = fmaxf(TINY, f + TINY);
  float g = -logf(-logf(u));
  float z = (logits[row * 32 + lane] + g) * 5.0f;
  float mx = z;
#pragma unroll
  for (int s = 16; s; s >>= 1) mx = fmaxf(mx, __shfl_xor_sync(0xffffffffu, mx, s));
  float e = expf(z - mx);
  float sm = e;
#pragma unroll
  for (int s = 16; s; s >>= 1) sm += __shfl_xor_sync(0xffffffffu, sm, s);
  out[row * 32 + lane] = e / sm;
}

// ---------------- lat[32,64] += ih^T @ icge, both modalities (lat pre-zeroed) ----------------
__global__ void lat_both_kernel(const float* __restrict__ w0, const float* __restrict__ w1,
                                const float* __restrict__ icge,
                                float* __restrict__ lat0, float* __restrict__ lat1, int chunk) {
  const float* w = blockIdx.y ? w1 : w0;
  float* lat = blockIdx.y ? lat1 : lat0;
  int lane = threadIdx.x & 31;
  int kg = threadIdx.x >> 5;
  int start = blockIdx.x * chunk;
  int end = min(start + chunk, NITEMS);
  float acc[8] = {0, 0, 0, 0, 0, 0, 0, 0};
  for (int it = start; it < end; ++it) {
    float wv = w[it * HH + lane];
    const float* cr = icge + it * EK + kg * 8;
#pragma unroll
    for (int j = 0; j < 8; j++) acc[j] = fmaf(wv, __ldg(cr + j), acc[j]);
  }
#pragma unroll
  for (int j = 0; j < 8; j++) atomicAdd(&lat[lane * EK + kg * 8 + j], acc[j]);
}

// ---------------- fused hyper-apply + final, warp per row ----------------
#define OI   (NUSERS * EK)
#define OHVU ((NUSERS + NITEMS) * EK)
#define OHVI (OHVU + NUSERS * EK)
#define OHTU (OHVI + NITEMS * EK)
#define OHTI (OHTU + NUSERS * EK)
__global__ void final_fused(float* __restrict__ out, const float* __restrict__ cge,
                            const float* __restrict__ m1a, const float* __restrict__ m1b,
                            const float* __restrict__ ih0, const float* __restrict__ ih1,
                            const float* __restrict__ uh0, const float* __restrict__ uh1,
                            const float* __restrict__ lat0, const float* __restrict__ lat1) {
  __shared__ float slA[HH * EK];
  __shared__ float slB[HH * EK];
  for (int t = threadIdx.x; t < HH * EK; t += 256) { slA[t] = lat0[t]; slB[t] = lat1[t]; }
  __syncthreads();
  int row = blockIdx.x * 8 + (threadIdx.x >> 5);
  if (row >= NNODES) return;
  int lane = threadIdx.x & 31;
  const float* w0;
  const float* w1;
  float *outV, *outT, *dst;
  if (row < NUSERS) {
    w0 = uh0 + row * HH; w1 = uh1 + row * HH;
    outV = out + OHVU + row * EK; outT = out + OHTU + row * EK;
    dst = out + row * EK;
  } else {
    int ir = row - NUSERS;
    w0 = ih0 + ir * HH; w1 = ih1 + ir * HH;
    outV = out + OHVI + ir * EK; outT = out + OHTI + ir * EK;
    dst = out + OI + ir * EK;
  }
  float wl0 = w0[lane], wl1 = w1[lane];
  float s0 = 0.f, s1 = 0.f, t0 = 0.f, t1 = 0.f;
#pragma unroll
  for (int h = 0; h < HH; h++) {
    float wv0 = __shfl_sync(0xffffffffu, wl0, h);
    float wv1 = __shfl_sync(0xffffffffu, wl1, h);
    s0 = fmaf(wv0, slA[h * EK + lane], s0);
    s1 = fmaf(wv0, slA[h * EK + lane + 32], s1);
    t0 = fmaf(wv1, slB[h * EK + lane], t0);
    t1 = fmaf(wv1, slB[h * EK + lane + 32], t1);
  }
  outV[lane] = s0; outV[lane + 32] = s1;
  outT[lane] = t0; outT[lane + 32] = t1;
  int b = row * EK;
  float a0 = m1a[b + lane], a1 = m1a[b + lane + 32];
  float c0 = m1b[b + lane], c1 = m1b[b + lane + 32];
  float g0 = s0 + t0, g1 = s1 + t1;
  float sa = a0 * a0 + a1 * a1;
  float sc = c0 * c0 + c1 * c1;
  float sg = g0 * g0 + g1 * g1;
#pragma unroll
  for (int s = 16; s; s >>= 1) {
    sa += __shfl_xor_sync(0xffffffffu, sa, s);
    sc += __shfl_xor_sync(0xffffffffu, sc, s);
    sg += __shfl_xor_sync(0xffffffffu, sg, s);
  }
  float ia = 1.0f / fmaxf(sqrtf(sa), 1e-12f);
  float ic = 1.0f / fmaxf(sqrtf(sc), 1e-12f);
  float ig = 0.2f / fmaxf(sqrtf(sg), 1e-12f);
  dst[lane]      = cge[b + lane]      + a0 * ia + c0 * ic + g0 * ig;
  dst[lane + 32] = cge[b + lane + 32] + a1 * ia + c1 * ic + g1 * ig;
}

// ================================================================================
extern "C" void kernel_launch(void* const* d_in, const int* in_sizes, int n_in,
                              void* d_out, int out_size) {
  const float* Gu       = (const float*)d_in[0];
  const float* Gi       = (const float*)d_in[1];
  const float* feat_v   = (const float*)d_in[2];
  const float* feat_t   = (const float*)d_in[3];
  const float* trs_v    = (const float*)d_in[4];
  const float* trs_t    = (const float*)d_in[5];
  const float* hyp_v    = (const float*)d_in[6];
  const float* hyp_t    = (const float*)d_in[7];
  const float* inv      = (const float*)d_in[8];
  const float* adj_vals = (const float*)d_in[9];
  const float* r_vals   = (const float*)d_in[10];
  const int*   adj_rows = (const int*)d_in[11];
  const int*   adj_cols = (const int*)d_in[12];
  const int*   r_rows   = (const int*)d_in[13];
  const int*   r_cols   = (const int*)d_in[14];
  float* out = (float*)d_out;
  int Fv = in_sizes[2] / NITEMS;
  int Ft = in_sizes[3] / NITEMS;

  float *p_itf, *p_ihl, *p_uhl, *p_ih, *p_uh, *p_e0, *p_e1, *p_m0, *p_m1, *p_lat;
  int *p_hist, *pA_cur, *pA_scol, *pA_csum, *pA_coff;
  int *pR_cur, *pR_scol, *pR_csum, *pR_coff;
  float *pA_sval, *pR_sval;
  cudaGetSymbolAddress((void**)&p_itf, g_itf);
  cudaGetSymbolAddress((void**)&p_ihl, g_ihl);
  cudaGetSymbolAddress((void**)&p_uhl, g_uhl);
  cudaGetSymbolAddress((void**)&p_ih,  g_ih);
  cudaGetSymbolAddress((void**)&p_uh,  g_uh);
  cudaGetSymbolAddress((void**)&p_e0,  g_e0);
  cudaGetSymbolAddress((void**)&p_e1,  g_e1);
  cudaGetSymbolAddress((void**)&p_m0,  g_m0);
  cudaGetSymbolAddress((void**)&p_m1,  g_m1);
  cudaGetSymbolAddress((void**)&p_lat, g_lat);
  cudaGetSymbolAddress((void**)&p_hist, g_hist);
  cudaGetSymbolAddress((void**)&pA_cur,  g_curA);
  cudaGetSymbolAddress((void**)&pA_scol, g_scolA);
  cudaGetSymbolAddress((void**)&pA_sval, g_svalA);
  cudaGetSymbolAddress((void**)&pA_csum, g_csumA);
  cudaGetSymbolAddress((void**)&pA_coff, g_coffA);
  cudaGetSymbolAddress((void**)&pR_cur,  g_curR);
  cudaGetSymbolAddress((void**)&pR_scol, g_scolR);
  cudaGetSymbolAddress((void**)&pR_sval, g_svalR);
  cudaGetSymbolAddress((void**)&pR_csum, g_csumR);
  cudaGetSymbolAddress((void**)&pR_coff, g_coffR);
  int* pA_start = p_hist;
  int* pR_start = p_hist + NNODES + 1;
  float* p_itfT = p_itf + NITEMS * EK;
  float* p_ihlT = p_ihl + NITEMS * HH;
  float* p_uhlT = p_uhl + NUSERS * HH;
  float* p_ihT  = p_ih + NITEMS * HH;
  float* p_uhT  = p_uh + NUSERS * HH;
  float* p_m0T  = p_m0 + NUSERS * EK;
  float* p_m1T  = p_m1 + NNODES * EK;
  float* p_latT = p_lat + HH * EK;

  // JAX threefry keys
  uint32_t ki0[2], ki1[2], ku0[2], ku1[2];
  for (int m = 0; m < 2; m++) {
    uint32_t km0, km1;
    tf2x32(0u, 42u, 0u, (uint32_t)m, &km0, &km1);
    tf2x32(km0, km1, 0u, 0u, &ki0[m], &ki1[m]);
    tf2x32(km0, km1, 0u, 1u, &ku0[m], &ku1[m]);
  }

  const int GADJE = (NNZADJ + 255) / 256;
  const int GRE   = (NNZR + 255) / 256;
  const int GNODE = (NNODES + 7) / 8;
  const int GUSER = (NUSERS + 7) / 8;

  // ---- zero CSR histograms (one memset) + lat ----
  cudaMemsetAsync(p_hist, 0, (NNODES + NUSERS + 2) * sizeof(int), 0);
  cudaMemsetAsync(p_lat, 0, 2 * HH * EK * sizeof(float), 0);

  // ---- both GEMMs (bf16x3 tensor cores) ----
  gemm_both_kernel<<<dim3((NITEMS + 127) / 128, 2), 256>>>(
      feat_v, feat_t, trs_v, trs_t, hyp_v, hyp_t,
      p_itf, p_itfT, p_ihl, p_ihlT, Fv, Ft);

  // ---- CSR builds (adj + r), merged launches ----
  csr_hist2<<<GADJE + GRE, 256>>>(adj_rows, r_rows, NNZADJ, NNZR, GADJE, pA_start, pR_start);
  csr_chunksum2<<<NCHA + NCHR, 256>>>(pA_start, pR_start, pA_csum, pR_csum, NNODES, NUSERS);
  csr_scanchunks2<<<2, 32>>>(pA_csum, pA_coff, pA_start, pR_csum, pR_coff, pR_start);
  csr_chunkscan2<<<NCHA + NCHR, 256>>>(pA_start, pA_coff, pA_cur,
                                       pR_start, pR_coff, pR_cur, NNODES, NUSERS);
  csr_scatter2<<<GADJE + GRE, 256>>>(adj_rows, adj_cols, adj_vals, pA_cur, pA_scol, pA_sval,
                                     r_rows, r_cols, r_vals, pR_cur, pR_scol, pR_sval,
                                     NNZADJ, NNZR, GADJE);

  // ---- cge chain (gather, combine fused into pass 2) ----
  spmm_csr_cge1<<<GNODE, 256>>>(pA_start, pA_scol, pA_sval,
                                (const float2*)Gu, (const float2*)Gi, (float2*)p_e1);
  spmm_csr_cge2<<<GNODE, 256>>>(pA_start, pA_scol, pA_sval, (const float2*)p_e1,
                                (const float2*)Gu, (const float2*)Gi, (float2*)p_e0);

  // ---- gumbel (items) ----
  gumbel_both_kernel<<<dim3((NITEMS + 7) / 8, 2), 256>>>(
      p_ihl, p_ihlT, p_ih, p_ihT, NITEMS, ki0[0], ki1[0], ki0[1], ki1[1]);

  // ---- fused r-spmms (one CSR-R read, two gathers) ----
  spmm_r_fused<<<dim3(GUSER, 2), 256>>>(pR_start, pR_scol, pR_sval,
                                        p_ihl, p_ihlT,
                                        (const float2*)p_itf, (const float2*)p_itfT,
                                        p_uhl, p_uhlT, (float2*)p_m0, (float2*)p_m0T);
  gumbel_both_kernel<<<dim3(GUSER, 2), 256>>>(
      p_uhl, p_uhlT, p_uh, p_uhT, NUSERS, ku0[0], ku1[0], ku0[1], ku1[1]);

  // ---- mge adj pass (gather) ----
  spmm_csr_mge_both<<<dim3(GNODE, 2), 256>>>(pA_start, pA_scol, pA_sval,
                                             (const float2*)p_m0, (const float2*)p_m0T,
                                             (const float2*)p_itf, (const float2*)p_itfT,
                                             inv, (float2*)p_m1, (float2*)p_m1T);

  // ---- hyper path + final (fused) ----
  lat_both_kernel<<<dim3(120, 2), 256>>>(p_ih, p_ihT, p_e0 + NUSERS * EK, p_lat, p_latT, 250);
  final_fused<<<GNODE, 256>>>(out, p_e0, p_m1, p_m1T,
                              p_ih, p_ihT, p_uh, p_uhT, p_lat, p_latT);
}

// round 11
// speedup vs baseline: 1.8336x; 1.1030x over previous
#include <cuda_runtime.h>
#include <stdint.h>

#define NUSERS 50000
#define NITEMS 30000
#define NNODES 80000
#define EK 64
#define HH 32
#define NNZADJ 2000000
#define NNZR 1000000
#define NCHA ((NNODES + 1023) / 1024)
#define NCHR ((NUSERS + 1023) / 1024)
#define GEMMB 235                       // (NITEMS+127)/128
#define GADJE ((NNZADJ + 255) / 256)
#define GRE   ((NNZR + 255) / 256)
#define GUSERB ((NUSERS + 7) / 8)       // 6250
#define GITMB  ((NITEMS + 7) / 8)       // 3750
#define GNODEB ((NNODES + 7) / 8)       // 10000
#define GCGEB  (GNODEB / 2)             // 5000 per y

// ---------------- scratch (device globals; allocation is forbidden) ----------------
__device__ float g_itf[2][NITEMS * EK];
__device__ float g_ihl[2][NITEMS * HH];
__device__ float g_uhl[2][NUSERS * HH];
__device__ float g_ih[2][NITEMS * HH];
__device__ float g_uh[2][NUSERS * HH];
__device__ float g_e0[NNODES * EK];      // cge
__device__ float g_e1[NNODES * EK];
__device__ float g_m0[2][NUSERS * EK];
__device__ float g_m1[2][NNODES * EK];
__device__ float g_lat[2][HH * EK];
// CSR scratch (histA and histR in ONE buffer so one memset clears both)
__device__ int   g_hist[NNODES + 1 + NUSERS + 1];
__device__ int   g_curA[NNODES];
__device__ int   g_scolA[NNZADJ];
__device__ float g_svalA[NNZADJ];
__device__ int   g_csumA[NCHA];
__device__ int   g_coffA[NCHA];
__device__ int   g_curR[NUSERS];
__device__ int   g_scolR[NNZR];
__device__ float g_svalR[NNZR];
__device__ int   g_csumR[NCHR];
__device__ int   g_coffR[NCHR];

// ---------------- threefry2x32 (JAX-compatible, 20 rounds) ----------------
__host__ __device__ __forceinline__ void tf2x32(uint32_t k0, uint32_t k1,
                                                uint32_t x0, uint32_t x1,
                                                uint32_t* o0, uint32_t* o1) {
  uint32_t ks2 = k0 ^ k1 ^ 0x1BD11BDAu;
  uint32_t v0 = x0 + k0, v1 = x1 + k1;
#define TFR(r) { v0 += v1; v1 = (v1 << (r)) | (v1 >> (32 - (r))); v1 ^= v0; }
  TFR(13) TFR(15) TFR(26) TFR(6)
  v0 += k1;  v1 += ks2 + 1u;
  TFR(17) TFR(29) TFR(16) TFR(24)
  v0 += ks2; v1 += k0 + 2u;
  TFR(13) TFR(15) TFR(26) TFR(6)
  v0 += k0;  v1 += k1 + 3u;
  TFR(17) TFR(29) TFR(16) TFR(24)
  v0 += k1;  v1 += ks2 + 4u;
  TFR(13) TFR(15) TFR(26) TFR(6)
  v0 += ks2; v1 += k0 + 5u;
#undef TFR
  *o0 = v0; *o1 = v1;
}

// ---------------- bf16 split + mma helpers ----------------
__device__ __forceinline__ uint2 bf16split2(float x0, float x1) {
  uint32_t h;
  asm("cvt.rn.bf16x2.f32 %0, %1, %2;" : "=r"(h) : "f"(x1), "f"(x0));
  float h0 = __uint_as_float(h << 16);
  float h1 = __uint_as_float(h & 0xFFFF0000u);
  uint32_t l;
  asm("cvt.rn.bf16x2.f32 %0, %1, %2;" : "=r"(l) : "f"(x1 - h1), "f"(x0 - h0));
  return make_uint2(h, l);
}

__device__ __forceinline__ void mma16(float* c, const uint32_t* a, const uint32_t* b) {
  asm volatile("mma.sync.aligned.m16n8k16.row.col.f32.bf16.bf16.f32 "
               "{%0,%1,%2,%3}, {%4,%5,%6,%7}, {%8,%9}, {%0,%1,%2,%3};"
               : "+f"(c[0]), "+f"(c[1]), "+f"(c[2]), "+f"(c[3])
               : "r"(a[0]), "r"(a[1]), "r"(a[2]), "r"(a[3]), "r"(b[0]), "r"(b[1]));
}

// ---------------- gumbel softmax row helper ----------------
__device__ __forceinline__ void gumbel_row(const float* __restrict__ logits,
                                           float* __restrict__ out,
                                           int row, int lane, unsigned k0, unsigned k1) {
  unsigned idx = (unsigned)row * 32u + (unsigned)lane;
  unsigned b0, b1;
  tf2x32(k0, k1, 0u, idx, &b0, &b1);
  unsigned bits = b0 ^ b1;
  float f = __uint_as_float((bits >> 9) | 0x3f800000u) - 1.0f;
  const float TINY = 1.1754943508222875e-38f;
  float u = fmaxf(TINY, f + TINY);
  float g = -logf(-logf(u));
  float z = (logits[row * 32 + lane] + g) * 5.0f;
  float mx = z;
#pragma unroll
  for (int s = 16; s; s >>= 1) mx = fmaxf(mx, __shfl_xor_sync(0xffffffffu, mx, s));
  float e = expf(z - mx);
  float sm = e;
#pragma unroll
  for (int s = 16; s; s >>= 1) sm += __shfl_xor_sync(0xffffffffu, sm, s);
  out[row * 32 + lane] = e / sm;
}

// ================= fused GEMM(bf16x3) + CSR histogram, one launch =================
// blockIdx.x < GEMMB: gemm block; else histogram block (y=0: adj, y=1: r).
#define ASP 132
#define BSP 100
__global__ __launch_bounds__(256, 2)
void gemm_hist_kernel(const float* __restrict__ A0, const float* __restrict__ A1,
                      const float* __restrict__ Bt0, const float* __restrict__ Bt1,
                      const float* __restrict__ Bh0, const float* __restrict__ Bh1,
                      float* __restrict__ Cf0, float* __restrict__ Cf1,
                      float* __restrict__ Cl0, float* __restrict__ Cl1,
                      int F0, int F1,
                      const int* __restrict__ rowsA, const int* __restrict__ rowsR,
                      int* __restrict__ cntA, int* __restrict__ cntR) {
  if (blockIdx.x >= GEMMB) {
    int hb = blockIdx.x - GEMMB;
    if (blockIdx.y == 0) {
      int e = hb * 256 + threadIdx.x;
      if (e < NNZADJ) atomicAdd(&cntA[__ldg(rowsA + e)], 1);
    } else {
      if (hb < GRE) {
        int e = hb * 256 + threadIdx.x;
        if (e < NNZR) atomicAdd(&cntR[__ldg(rowsR + e)], 1);
      }
    }
    return;
  }
  __shared__ uint2 AsP[16][ASP];
  __shared__ uint2 BsP[16][BSP];
  const int mmod = blockIdx.y;
  const float* A  = mmod ? A1 : A0;
  const float* Bt = mmod ? Bt1 : Bt0;
  const float* Bh = mmod ? Bh1 : Bh0;
  float* Cf = mmod ? Cf1 : Cf0;
  float* Cl = mmod ? Cl1 : Cl0;
  const int F = mmod ? F1 : F0;

  const int row0 = blockIdx.x * 128;
  const int tid = threadIdx.x;
  const int wid = tid >> 5, lane = tid & 31;
  const int wr = wid >> 1, wc = wid & 1;
  const int qid = lane >> 2, qtid = lane & 3;

  const int lr = tid >> 1;
  const int lk2 = (tid & 1) * 8;
  const int gr_l = row0 + lr;
  const bool rok = gr_l < NITEMS;
  const float* Arow = A + (size_t)gr_l * F + lk2 * 2;

  float4 a4[4];
  float bb0[6], bb1[6];
  const float4 z4 = make_float4(0.f, 0.f, 0.f, 0.f);
#pragma unroll
  for (int i = 0; i < 4; i++) a4[i] = rok ? __ldg((const float4*)(Arow + 4 * i)) : z4;
#pragma unroll
  for (int i = 0; i < 6; i++) {
    int p = tid + 256 * i, k2 = p / 96, c = p - k2 * 96;
    int kk = 2 * k2;
    if (c < 64) { bb0[i] = __ldg(Bt + kk * 64 + c); bb1[i] = __ldg(Bt + (kk + 1) * 64 + c); }
    else        { bb0[i] = __ldg(Bh + kk * 32 + c - 64); bb1[i] = __ldg(Bh + (kk + 1) * 32 + c - 64); }
  }

  float acc[2][6][4];
#pragma unroll
  for (int mt = 0; mt < 2; mt++)
#pragma unroll
    for (int nt = 0; nt < 6; nt++)
#pragma unroll
      for (int j = 0; j < 4; j++) acc[mt][nt][j] = 0.0f;

  for (int k0 = 0; k0 < F; k0 += 32) {
    float av[16];
#pragma unroll
    for (int i = 0; i < 4; i++) {
      av[4 * i + 0] = a4[i].x; av[4 * i + 1] = a4[i].y;
      av[4 * i + 2] = a4[i].z; av[4 * i + 3] = a4[i].w;
    }
#pragma unroll
    for (int j = 0; j < 8; j++)
      AsP[lk2 + j][lr] = bf16split2(av[2 * j], av[2 * j + 1]);
#pragma unroll
    for (int i = 0; i < 6; i++) {
      int p = tid + 256 * i, k2 = p / 96, c = p - k2 * 96;
      BsP[k2][c] = bf16split2(bb0[i], bb1[i]);
    }
    __syncthreads();
    int kn = k0 + 32;
    if (kn < F) {
#pragma unroll
      for (int i = 0; i < 4; i++) a4[i] = rok ? __ldg((const float4*)(Arow + kn + 4 * i)) : z4;
#pragma unroll
      for (int i = 0; i < 6; i++) {
        int p = tid + 256 * i, k2 = p / 96, c = p - k2 * 96;
        int kk = kn + 2 * k2;
        if (c < 64) { bb0[i] = __ldg(Bt + kk * 64 + c); bb1[i] = __ldg(Bt + (kk + 1) * 64 + c); }
        else        { bb0[i] = __ldg(Bh + kk * 32 + c - 64); bb1[i] = __ldg(Bh + (kk + 1) * 32 + c - 64); }
      }
    }
#pragma unroll
    for (int ks = 0; ks < 2; ks++) {
      const int kb = ks * 8;
      uint2 a2[2][4];
#pragma unroll
      for (int mt = 0; mt < 2; mt++) {
        int ar = wr * 32 + mt * 16 + qid;
        a2[mt][0] = AsP[kb + qtid][ar];
        a2[mt][1] = AsP[kb + qtid][ar + 8];
        a2[mt][2] = AsP[kb + qtid + 4][ar];
        a2[mt][3] = AsP[kb + qtid + 4][ar + 8];
      }
#pragma unroll
      for (int nt = 0; nt < 6; nt++) {
        int bn = wc * 48 + nt * 8 + qid;
        uint2 b0 = BsP[kb + qtid][bn];
        uint2 b1 = BsP[kb + qtid + 4][bn];
        uint32_t bhv[2] = {b0.x, b1.x};
        uint32_t blv[2] = {b0.y, b1.y};
#pragma unroll
        for (int mt = 0; mt < 2; mt++) {
          uint32_t ah[4] = {a2[mt][0].x, a2[mt][1].x, a2[mt][2].x, a2[mt][3].x};
          uint32_t al[4] = {a2[mt][0].y, a2[mt][1].y, a2[mt][2].y, a2[mt][3].y};
          mma16(acc[mt][nt], ah, bhv);
          mma16(acc[mt][nt], ah, blv);
          mma16(acc[mt][nt], al, bhv);
        }
      }
    }
    __syncthreads();
  }

#pragma unroll
  for (int mt = 0; mt < 2; mt++) {
    int gr = row0 + wr * 32 + mt * 16 + qid;
#pragma unroll
    for (int nt = 0; nt < 6; nt++) {
      int cc = wc * 48 + nt * 8 + 2 * qtid;
      if (gr < NITEMS) {
        if (cc < 64) { Cf[gr * 64 + cc] = acc[mt][nt][0]; Cf[gr * 64 + cc + 1] = acc[mt][nt][1]; }
        else         { Cl[gr * 32 + cc - 64] = acc[mt][nt][0]; Cl[gr * 32 + cc - 63] = acc[mt][nt][1]; }
      }
      if (gr + 8 < NITEMS) {
        if (cc < 64) { Cf[(gr + 8) * 64 + cc] = acc[mt][nt][2]; Cf[(gr + 8) * 64 + cc + 1] = acc[mt][nt][3]; }
        else         { Cl[(gr + 8) * 32 + cc - 64] = acc[mt][nt][2]; Cl[(gr + 8) * 32 + cc - 63] = acc[mt][nt][3]; }
      }
    }
  }
}

// ================= CSR scans + scatter (unchanged) =================
__global__ void csr_chunksum2(const int* __restrict__ cntA, const int* __restrict__ cntB,
                              int* __restrict__ csumA, int* __restrict__ csumB,
                              int nA, int nB) {
  __shared__ int ts[256];
  const int* cnt;
  int* csum;
  int n, ch;
  if (blockIdx.x < NCHA) { cnt = cntA; csum = csumA; n = nA; ch = blockIdx.x; }
  else                   { cnt = cntB; csum = csumB; n = nB; ch = blockIdx.x - NCHA; }
  int base = ch * 1024;
  int s = 0;
  for (int i = threadIdx.x; i < 1024; i += 256) {
    int idx = base + i;
    s += (idx < n) ? cnt[idx] : 0;
  }
  ts[threadIdx.x] = s;
  __syncthreads();
  for (int off = 128; off; off >>= 1) {
    if (threadIdx.x < off) ts[threadIdx.x] += ts[threadIdx.x + off];
    __syncthreads();
  }
  if (threadIdx.x == 0) csum[ch] = ts[0];
}

__global__ void csr_scanchunks2(const int* __restrict__ csumA, int* __restrict__ coffA,
                                int* __restrict__ startA,
                                const int* __restrict__ csumB, int* __restrict__ coffB,
                                int* __restrict__ startB) {
  if (threadIdx.x != 0) return;
  if (blockIdx.x == 0) {
    int run = 0;
    for (int i = 0; i < NCHA; i++) { coffA[i] = run; run += csumA[i]; }
    startA[NNODES] = NNZADJ;
  } else {
    int run = 0;
    for (int i = 0; i < NCHR; i++) { coffB[i] = run; run += csumB[i]; }
    startB[NUSERS] = NNZR;
  }
}

__global__ void csr_chunkscan2(int* __restrict__ cntA, const int* __restrict__ coffA,
                               int* __restrict__ curA,
                               int* __restrict__ cntB, const int* __restrict__ coffB,
                               int* __restrict__ curB, int nA, int nB) {
  __shared__ int sm[1024];
  __shared__ int ts[256];
  int* cnt;
  const int* coff;
  int* cur;
  int n, ch;
  if (blockIdx.x < NCHA) { cnt = cntA; coff = coffA; cur = curA; n = nA; ch = blockIdx.x; }
  else                   { cnt = cntB; coff = coffB; cur = curB; n = nB; ch = blockIdx.x - NCHA; }
  int base = ch * 1024;
  for (int i = threadIdx.x; i < 1024; i += 256)
    sm[i] = (base + i < n) ? cnt[base + i] : 0;
  __syncthreads();
  int t = threadIdx.x;
  int a0 = sm[t * 4], a1 = sm[t * 4 + 1], a2 = sm[t * 4 + 2], a3 = sm[t * 4 + 3];
  int local = a0 + a1 + a2 + a3;
  ts[t] = local;
  __syncthreads();
  for (int off = 1; off < 256; off <<= 1) {
    int v = (t >= off) ? ts[t - off] : 0;
    __syncthreads();
    ts[t] += v;
    __syncthreads();
  }
  int excl = ts[t] - local + coff[ch];
  int i0 = base + t * 4;
  if (i0 + 0 < n) { cnt[i0 + 0] = excl;                cur[i0 + 0] = excl; }
  if (i0 + 1 < n) { cnt[i0 + 1] = excl + a0;           cur[i0 + 1] = excl + a0; }
  if (i0 + 2 < n) { cnt[i0 + 2] = excl + a0 + a1;      cur[i0 + 2] = excl + a0 + a1; }
  if (i0 + 3 < n) { cnt[i0 + 3] = excl + a0 + a1 + a2; cur[i0 + 3] = excl + a0 + a1 + a2; }
}

__global__ void csr_scatter2(const int* __restrict__ rowsA, const int* __restrict__ colsA,
                             const float* __restrict__ valsA, int* __restrict__ curA,
                             int* __restrict__ scolA, float* __restrict__ svalA,
                             const int* __restrict__ rowsB, const int* __restrict__ colsB,
                             const float* __restrict__ valsB, int* __restrict__ curB,
                             int* __restrict__ scolB, float* __restrict__ svalB) {
  int b = blockIdx.x;
  if (b < GADJE) {
    int e = b * 256 + threadIdx.x;
    if (e >= NNZADJ) return;
    int r = __ldg(rowsA + e);
    int p = atomicAdd(&curA[r], 1);
    scolA[p] = __ldg(colsA + e);
    svalA[p] = __ldg(valsA + e);
  } else {
    int e = (b - GADJE) * 256 + threadIdx.x;
    if (e >= NNZR) return;
    int r = __ldg(rowsB + e);
    int p = atomicAdd(&curB[r], 1);
    scolB[p] = __ldg(colsB + e);
    svalB[p] = __ldg(valsB + e);
  }
}

// ================= phase 2: r_fused + gumbel-items + cge1 in one launch =================
__global__ void phase2_kernel(const int* __restrict__ startR, const int* __restrict__ scolR,
                              const float* __restrict__ svalR,
                              const float* __restrict__ ihl0, const float* __restrict__ ihl1,
                              const float2* __restrict__ itf0, const float2* __restrict__ itf1,
                              float* __restrict__ uhl0, float* __restrict__ uhl1,
                              float2* __restrict__ m00, float2* __restrict__ m01,
                              float* __restrict__ ih0, float* __restrict__ ih1,
                              unsigned ki00, unsigned ki01, unsigned ki10, unsigned ki11,
                              const int* __restrict__ startA, const int* __restrict__ scolA,
                              const float* __restrict__ svalA,
                              const float2* __restrict__ Gu, const float2* __restrict__ Gi,
                              float2* __restrict__ e1) {
  int bx = blockIdx.x;
  int wid = threadIdx.x >> 5, lane = threadIdx.x & 31;
  if (bx < GUSERB) {
    // fused r-spmm: ihl[32]->uhl and itf[64]->m0, modality = blockIdx.y
    int row = bx * 8 + wid;
    if (row >= NUSERS) return;
    const float* xs = blockIdx.y ? ihl1 : ihl0;
    const float2* xd = blockIdx.y ? itf1 : itf0;
    float* ys = blockIdx.y ? uhl1 : uhl0;
    float2* yd = blockIdx.y ? m01 : m00;
    int s = startR[row], e = startR[row + 1];
    float a = 0.f, ax = 0.f, ay = 0.f;
    int i = s;
    for (; i + 1 < e; i += 2) {
      int c0 = __ldg(scolR + i), c1 = __ldg(scolR + i + 1);
      float v0 = __ldg(svalR + i), v1 = __ldg(svalR + i + 1);
      float s0 = __ldg(xs + (size_t)c0 * 32 + lane);
      float s1 = __ldg(xs + (size_t)c1 * 32 + lane);
      float2 d0 = __ldg(xd + (size_t)c0 * 32 + lane);
      float2 d1 = __ldg(xd + (size_t)c1 * 32 + lane);
      a = fmaf(v0, s0, a); ax = fmaf(v0, d0.x, ax); ay = fmaf(v0, d0.y, ay);
      a = fmaf(v1, s1, a); ax = fmaf(v1, d1.x, ax); ay = fmaf(v1, d1.y, ay);
    }
    for (; i < e; i++) {
      int c = __ldg(scolR + i);
      float v = __ldg(svalR + i);
      a = fmaf(v, __ldg(xs + (size_t)c * 32 + lane), a);
      float2 d = __ldg(xd + (size_t)c * 32 + lane);
      ax = fmaf(v, d.x, ax); ay = fmaf(v, d.y, ay);
    }
    ys[(size_t)row * 32 + lane] = a;
    yd[(size_t)row * 32 + lane] = make_float2(ax, ay);
  } else if (bx < GUSERB + GITMB) {
    // gumbel items, modality = blockIdx.y
    int row = (bx - GUSERB) * 8 + wid;
    if (row >= NITEMS) return;
    const float* lg = blockIdx.y ? ihl1 : ihl0;
    float* o = blockIdx.y ? ih1 : ih0;
    unsigned k0 = blockIdx.y ? ki10 : ki00;
    unsigned k1 = blockIdx.y ? ki11 : ki01;
    gumbel_row(lg, o, row, lane, k0, k1);
  } else {
    // cge1: rows split across y
    int row = ((bx - GUSERB - GITMB) + blockIdx.y * GCGEB) * 8 + wid;
    if (row >= NNODES) return;
    int s = startA[row], e = startA[row + 1];
    float ax = 0.f, ay = 0.f;
    int i = s;
    for (; i + 1 < e; i += 2) {
      int c0 = __ldg(scolA + i), c1 = __ldg(scolA + i + 1);
      float v0 = __ldg(svalA + i), v1 = __ldg(svalA + i + 1);
      const float2* x0p = (c0 < NUSERS) ? Gu + (size_t)c0 * 32 : Gi + (size_t)(c0 - NUSERS) * 32;
      const float2* x1p = (c1 < NUSERS) ? Gu + (size_t)c1 * 32 : Gi + (size_t)(c1 - NUSERS) * 32;
      float2 x0 = __ldg(x0p + lane), x1 = __ldg(x1p + lane);
      ax = fmaf(v0, x0.x, ax); ay = fmaf(v0, x0.y, ay);
      ax = fmaf(v1, x1.x, ax); ay = fmaf(v1, x1.y, ay);
    }
    for (; i < e; i++) {
      int c = __ldg(scolA + i);
      float v = __ldg(svalA + i);
      const float2* xp = (c < NUSERS) ? Gu + (size_t)c * 32 : Gi + (size_t)(c - NUSERS) * 32;
      float2 xv = __ldg(xp + lane);
      ax = fmaf(v, xv.x, ax); ay = fmaf(v, xv.y, ay);
    }
    e1[(size_t)row * 32 + lane] = make_float2(ax, ay);
  }
}

// ================= phase 3: mega adj pass (cge2+combine, mge both) + gumbel-u =================
__global__ void phase3_kernel(const int* __restrict__ startA, const int* __restrict__ scolA,
                              const float* __restrict__ svalA,
                              const float2* __restrict__ e1,
                              const float2* __restrict__ Gu, const float2* __restrict__ Gi,
                              float2* __restrict__ cge,
                              const float2* __restrict__ m00, const float2* __restrict__ m01,
                              const float2* __restrict__ itf0, const float2* __restrict__ itf1,
                              const float* __restrict__ inv,
                              float2* __restrict__ m10, float2* __restrict__ m11,
                              const float* __restrict__ uhl0, const float* __restrict__ uhl1,
                              float* __restrict__ uh0, float* __restrict__ uh1,
                              unsigned ku00, unsigned ku01, unsigned ku10, unsigned ku11) {
  int bx = blockIdx.x;
  int wid = threadIdx.x >> 5, lane = threadIdx.x & 31;
  if (bx < GNODEB) {
    int row = bx * 8 + wid;
    if (row >= NNODES) return;
    int s = startA[row], e = startA[row + 1];
    float ex = 0.f, ey = 0.f;              // cge gather
    float vx = 0.f, vy = 0.f;              // mge visual
    float tx = 0.f, ty = 0.f;              // mge text
    for (int i = s; i < e; i++) {
      int c = __ldg(scolA + i);
      float v = __ldg(svalA + i);
      float2 ev = __ldg(e1 + (size_t)c * 32 + lane);
      float vm = v;
      const float2* sv;
      const float2* st;
      if (c < NUSERS) {
        vm = v * __ldg(inv + c);
        sv = m00 + (size_t)c * 32; st = m01 + (size_t)c * 32;
      } else {
        sv = itf0 + (size_t)(c - NUSERS) * 32; st = itf1 + (size_t)(c - NUSERS) * 32;
      }
      float2 dv = __ldg(sv + lane);
      float2 dt = __ldg(st + lane);
      ex = fmaf(v, ev.x, ex); ey = fmaf(v, ev.y, ey);
      vx = fmaf(vm, dv.x, vx); vy = fmaf(vm, dv.y, vy);
      tx = fmaf(vm, dt.x, tx); ty = fmaf(vm, dt.y, ty);
    }
    float2 ego = (row < NUSERS) ? __ldg(Gu + (size_t)row * 32 + lane)
                                : __ldg(Gi + (size_t)(row - NUSERS) * 32 + lane);
    float2 e1v = __ldg(e1 + (size_t)row * 32 + lane);
    cge[(size_t)row * 32 + lane] = make_float2((ego.x + e1v.x + ex) * (1.0f / 3.0f),
                                               (ego.y + e1v.y + ey) * (1.0f / 3.0f));
    m10[(size_t)row * 32 + lane] = make_float2(vx, vy);
    m11[(size_t)row * 32 + lane] = make_float2(tx, ty);
  } else if (bx < GNODEB + GUSERB) {
    int row = (bx - GNODEB) * 8 + wid;
    if (row >= NUSERS) return;
    gumbel_row(uhl0, uh0, row, lane, ku00, ku01);
  } else {
    int row = (bx - GNODEB - GUSERB) * 8 + wid;
    if (row >= NUSERS) return;
    gumbel_row(uhl1, uh1, row, lane, ku10, ku11);
  }
}

// ---------------- lat[32,64] += ih^T @ icge, both modalities (lat pre-zeroed) ----------------
__global__ void lat_both_kernel(const float* __restrict__ w0, const float* __restrict__ w1,
                                const float* __restrict__ icge,
                                float* __restrict__ lat0, float* __restrict__ lat1, int chunk) {
  const float* w = blockIdx.y ? w1 : w0;
  float* lat = blockIdx.y ? lat1 : lat0;
  int lane = threadIdx.x & 31;
  int kg = threadIdx.x >> 5;
  int start = blockIdx.x * chunk;
  int end = min(start + chunk, NITEMS);
  float acc[8] = {0, 0, 0, 0, 0, 0, 0, 0};
  for (int it = start; it < end; ++it) {
    float wv = w[it * HH + lane];
    const float* cr = icge + it * EK + kg * 8;
#pragma unroll
    for (int j = 0; j < 8; j++) acc[j] = fmaf(wv, __ldg(cr + j), acc[j]);
  }
#pragma unroll
  for (int j = 0; j < 8; j++) atomicAdd(&lat[lane * EK + kg * 8 + j], acc[j]);
}

// ---------------- fused hyper-apply + final, warp per row ----------------
#define OI   (NUSERS * EK)
#define OHVU ((NUSERS + NITEMS) * EK)
#define OHVI (OHVU + NUSERS * EK)
#define OHTU (OHVI + NITEMS * EK)
#define OHTI (OHTU + NUSERS * EK)
__global__ void final_fused(float* __restrict__ out, const float* __restrict__ cge,
                            const float* __restrict__ m1a, const float* __restrict__ m1b,
                            const float* __restrict__ ih0, const float* __restrict__ ih1,
                            const float* __restrict__ uh0, const float* __restrict__ uh1,
                            const float* __restrict__ lat0, const float* __restrict__ lat1) {
  __shared__ float slA[HH * EK];
  __shared__ float slB[HH * EK];
  for (int t = threadIdx.x; t < HH * EK; t += 256) { slA[t] = lat0[t]; slB[t] = lat1[t]; }
  __syncthreads();
  int row = blockIdx.x * 8 + (threadIdx.x >> 5);
  if (row >= NNODES) return;
  int lane = threadIdx.x & 31;
  const float* w0;
  const float* w1;
  float *outV, *outT, *dst;
  if (row < NUSERS) {
    w0 = uh0 + row * HH; w1 = uh1 + row * HH;
    outV = out + OHVU + row * EK; outT = out + OHTU + row * EK;
    dst = out + row * EK;
  } else {
    int ir = row - NUSERS;
    w0 = ih0 + ir * HH; w1 = ih1 + ir * HH;
    outV = out + OHVI + ir * EK; outT = out + OHTI + ir * EK;
    dst = out + OI + ir * EK;
  }
  float wl0 = w0[lane], wl1 = w1[lane];
  float s0 = 0.f, s1 = 0.f, t0 = 0.f, t1 = 0.f;
#pragma unroll
  for (int h = 0; h < HH; h++) {
    float wv0 = __shfl_sync(0xffffffffu, wl0, h);
    float wv1 = __shfl_sync(0xffffffffu, wl1, h);
    s0 = fmaf(wv0, slA[h * EK + lane], s0);
    s1 = fmaf(wv0, slA[h * EK + lane + 32], s1);
    t0 = fmaf(wv1, slB[h * EK + lane], t0);
    t1 = fmaf(wv1, slB[h * EK + lane + 32], t1);
  }
  outV[lane] = s0; outV[lane + 32] = s1;
  outT[lane] = t0; outT[lane + 32] = t1;
  int b = row * EK;
  float a0 = m1a[b + lane], a1 = m1a[b + lane + 32];
  float c0 = m1b[b + lane], c1 = m1b[b + lane + 32];
  float g0 = s0 + t0, g1 = s1 + t1;
  float sa = a0 * a0 + a1 * a1;
  float sc = c0 * c0 + c1 * c1;
  float sg = g0 * g0 + g1 * g1;
#pragma unroll
  for (int s = 16; s; s >>= 1) {
    sa += __shfl_xor_sync(0xffffffffu, sa, s);
    sc += __shfl_xor_sync(0xffffffffu, sc, s);
    sg += __shfl_xor_sync(0xffffffffu, sg, s);
  }
  float ia = 1.0f / fmaxf(sqrtf(sa), 1e-12f);
  float ic = 1.0f / fmaxf(sqrtf(sc), 1e-12f);
  float ig = 0.2f / fmaxf(sqrtf(sg), 1e-12f);
  dst[lane]      = cge[b + lane]      + a0 * ia + c0 * ic + g0 * ig;
  dst[lane + 32] = cge[b + lane + 32] + a1 * ia + c1 * ic + g1 * ig;
}

// ================================================================================
extern "C" void kernel_launch(void* const* d_in, const int* in_sizes, int n_in,
                              void* d_out, int out_size) {
  const float* Gu       = (const float*)d_in[0];
  const float* Gi       = (const float*)d_in[1];
  const float* feat_v   = (const float*)d_in[2];
  const float* feat_t   = (const float*)d_in[3];
  const float* trs_v    = (const float*)d_in[4];
  const float* trs_t    = (const float*)d_in[5];
  const float* hyp_v    = (const float*)d_in[6];
  const float* hyp_t    = (const float*)d_in[7];
  const float* inv      = (const float*)d_in[8];
  const float* adj_vals = (const float*)d_in[9];
  const float* r_vals   = (const float*)d_in[10];
  const int*   adj_rows = (const int*)d_in[11];
  const int*   adj_cols = (const int*)d_in[12];
  const int*   r_rows   = (const int*)d_in[13];
  const int*   r_cols   = (const int*)d_in[14];
  float* out = (float*)d_out;
  int Fv = in_sizes[2] / NITEMS;
  int Ft = in_sizes[3] / NITEMS;

  float *p_itf, *p_ihl, *p_uhl, *p_ih, *p_uh, *p_e0, *p_e1, *p_m0, *p_m1, *p_lat;
  int *p_hist, *pA_cur, *pA_scol, *pA_csum, *pA_coff;
  int *pR_cur, *pR_scol, *pR_csum, *pR_coff;
  float *pA_sval, *pR_sval;
  cudaGetSymbolAddress((void**)&p_itf, g_itf);
  cudaGetSymbolAddress((void**)&p_ihl, g_ihl);
  cudaGetSymbolAddress((void**)&p_uhl, g_uhl);
  cudaGetSymbolAddress((void**)&p_ih,  g_ih);
  cudaGetSymbolAddress((void**)&p_uh,  g_uh);
  cudaGetSymbolAddress((void**)&p_e0,  g_e0);
  cudaGetSymbolAddress((void**)&p_e1,  g_e1);
  cudaGetSymbolAddress((void**)&p_m0,  g_m0);
  cudaGetSymbolAddress((void**)&p_m1,  g_m1);
  cudaGetSymbolAddress((void**)&p_lat, g_lat);
  cudaGetSymbolAddress((void**)&p_hist, g_hist);
  cudaGetSymbolAddress((void**)&pA_cur,  g_curA);
  cudaGetSymbolAddress((void**)&pA_scol, g_scolA);
  cudaGetSymbolAddress((void**)&pA_sval, g_svalA);
  cudaGetSymbolAddress((void**)&pA_csum, g_csumA);
  cudaGetSymbolAddress((void**)&pA_coff, g_coffA);
  cudaGetSymbolAddress((void**)&pR_cur,  g_curR);
  cudaGetSymbolAddress((void**)&pR_scol, g_scolR);
  cudaGetSymbolAddress((void**)&pR_sval, g_svalR);
  cudaGetSymbolAddress((void**)&pR_csum, g_csumR);
  cudaGetSymbolAddress((void**)&pR_coff, g_coffR);
  int* pA_start = p_hist;
  int* pR_start = p_hist + NNODES + 1;
  float* p_itfT = p_itf + NITEMS * EK;
  float* p_ihlT = p_ihl + NITEMS * HH;
  float* p_uhlT = p_uhl + NUSERS * HH;
  float* p_ihT  = p_ih + NITEMS * HH;
  float* p_uhT  = p_uh + NUSERS * HH;
  float* p_m0T  = p_m0 + NUSERS * EK;
  float* p_m1T  = p_m1 + NNODES * EK;
  float* p_latT = p_lat + HH * EK;

  // JAX threefry keys
  uint32_t ki0[2], ki1[2], ku0[2], ku1[2];
  for (int m = 0; m < 2; m++) {
    uint32_t km0, km1;
    tf2x32(0u, 42u, 0u, (uint32_t)m, &km0, &km1);
    tf2x32(km0, km1, 0u, 0u, &ki0[m], &ki1[m]);
    tf2x32(km0, km1, 0u, 1u, &ku0[m], &ku1[m]);
  }

  // ---- zero CSR histograms (one memset) + lat ----
  cudaMemsetAsync(p_hist, 0, (NNODES + NUSERS + 2) * sizeof(int), 0);
  cudaMemsetAsync(p_lat, 0, 2 * HH * EK * sizeof(float), 0);

  // ---- GEMMs + CSR histograms in one launch ----
  gemm_hist_kernel<<<dim3(GEMMB + GADJE, 2), 256>>>(
      feat_v, feat_t, trs_v, trs_t, hyp_v, hyp_t,
      p_itf, p_itfT, p_ihl, p_ihlT, Fv, Ft,
      adj_rows, r_rows, pA_start, pR_start);

  // ---- CSR scans + scatter ----
  csr_chunksum2<<<NCHA + NCHR, 256>>>(pA_start, pR_start, pA_csum, pR_csum, NNODES, NUSERS);
  csr_scanchunks2<<<2, 32>>>(pA_csum, pA_coff, pA_start, pR_csum, pR_coff, pR_start);
  csr_chunkscan2<<<NCHA + NCHR, 256>>>(pA_start, pA_coff, pA_cur,
                                       pR_start, pR_coff, pR_cur, NNODES, NUSERS);
  csr_scatter2<<<GADJE + GRE, 256>>>(adj_rows, adj_cols, adj_vals, pA_cur, pA_scol, pA_sval,
                                     r_rows, r_cols, r_vals, pR_cur, pR_scol, pR_sval);

  // ---- phase 2: r_fused + gumbel-items + cge1 ----
  phase2_kernel<<<dim3(GUSERB + GITMB + GCGEB, 2), 256>>>(
      pR_start, pR_scol, pR_sval,
      p_ihl, p_ihlT, (const float2*)p_itf, (const float2*)p_itfT,
      p_uhl, p_uhlT, (float2*)p_m0, (float2*)p_m0T,
      p_ih, p_ihT, ki0[0], ki1[0], ki0[1], ki1[1],
      pA_start, pA_scol, pA_sval,
      (const float2*)Gu, (const float2*)Gi, (float2*)p_e1);

  // ---- phase 3: mega adj (cge2 + mge both) + gumbel-u ----
  phase3_kernel<<<GNODEB + 2 * GUSERB, 256>>>(
      pA_start, pA_scol, pA_sval, (const float2*)p_e1,
      (const float2*)Gu, (const float2*)Gi, (float2*)p_e0,
      (const float2*)p_m0, (const float2*)p_m0T,
      (const float2*)p_itf, (const float2*)p_itfT, inv,
      (float2*)p_m1, (float2*)p_m1T,
      p_uhl, p_uhlT, p_uh, p_uhT, ku0[0], ku1[0], ku0[1], ku1[1]);

  // ---- hyper path + final ----
  lat_both_kernel<<<dim3(120, 2), 256>>>(p_ih, p_ihT, p_e0 + NUSERS * EK, p_lat, p_latT, 250);
  final_fused<<<GNODEB, 256>>>(out, p_e0, p_m1, p_m1T,
                               p_ih, p_ihT, p_uh, p_uhT, p_lat, p_latT);
}